// round 4
// baseline (speedup 1.0000x reference)
#include <cuda_runtime.h>
#include <cstdint>
#include <cstddef>

#define NSN  100000
#define NMD  50000
#define EE   600000
#define D    128
#define HOR  8
#define NEG  0.2f
#define NBLK 96    // persistent rollout blocks (<= SM count, always co-resident)

// ---------------- device scratch ----------------
__device__ float    d_xl[(size_t)NSN * D];
__device__ float    d_xr[(size_t)NMD * D];
__device__ float    d_ew[EE];
__device__ unsigned d_menc[NMD];
__device__ float    d_ssum[NMD];
__device__ __align__(16) float d_gacc[D];
__device__ __align__(16) float d_inp[D];
__device__ __align__(16) float d_h[D];
__device__ __align__(16) float d_c[D];
__device__ __align__(16) float d_h2[D];
__device__ __align__(16) float d_gates[4 * D];
__device__ float    d_logits[NMD];
__device__ float    d_pm_best[NBLK];
__device__ int      d_pm_bi[NBLK];
__device__ float    d_pm_lm[NBLK];
__device__ float    d_pm_ls[NBLK];
__device__ uint2    d_keys[HOR];
__device__ int      d_is64;
// grid barrier state (zero-initialized at module load; barrier leaves cnt==0)
__device__ volatile unsigned d_bgen;
__device__ unsigned d_bcnt;

// ---------------- helpers ----------------
__device__ __forceinline__ int eidx(const void* ei, int is64, long long pos) {
    return is64 ? (int)((const long long*)ei)[pos] : ((const int*)ei)[pos];
}
__device__ __forceinline__ unsigned encf(float f) {
    unsigned b = __float_as_uint(f);
    return (b & 0x80000000u) ? ~b : (b | 0x80000000u);
}
__device__ __forceinline__ float decf(unsigned u) {
    return (u >> 31) ? __uint_as_float(u ^ 0x80000000u) : __uint_as_float(~u);
}
__device__ __forceinline__ float neginf() { return __int_as_float((int)0xff800000); }

// packed f32x2 FMA (B300: FFMA2 doubles fp32 fma-pipe throughput; PTX-only)
__device__ __forceinline__ unsigned long long pk2(float x) {
    unsigned long long r; asm("mov.b64 %0, {%1, %1};" : "=l"(r) : "f"(x)); return r;
}
__device__ __forceinline__ unsigned long long ffma2(unsigned long long a,
                                                   unsigned long long b,
                                                   unsigned long long c) {
    unsigned long long d_;
    asm("fma.rn.f32x2 %0, %1, %2, %3;" : "=l"(d_) : "l"(a), "l"(b), "l"(c));
    return d_;
}
__device__ __forceinline__ float2 upk2(unsigned long long v) {
    float lo, hi; asm("mov.b64 {%0, %1}, %2;" : "=f"(lo), "=f"(hi) : "l"(v));
    return make_float2(lo, hi);
}

// JAX threefry2x32, 20 rounds
__device__ __forceinline__ uint2 tf2x32(unsigned k0, unsigned k1, unsigned x0, unsigned x1) {
    unsigned k2 = k0 ^ k1 ^ 0x1BD11BDAu;
    x0 += k0; x1 += k1;
#define TFR(r) { x0 += x1; x1 = (x1 << (r)) | (x1 >> (32 - (r))); x1 ^= x0; }
    TFR(13) TFR(15) TFR(26) TFR(6)   x0 += k1; x1 += k2 + 1u;
    TFR(17) TFR(29) TFR(16) TFR(24)  x0 += k2; x1 += k0 + 2u;
    TFR(13) TFR(15) TFR(26) TFR(6)   x0 += k0; x1 += k1 + 3u;
    TFR(17) TFR(29) TFR(16) TFR(24)  x0 += k1; x1 += k2 + 4u;
    TFR(13) TFR(15) TFR(26) TFR(6)   x0 += k2; x1 += k0 + 5u;
#undef TFR
    return make_uint2(x0, x1);
}

// grid-wide barrier (generation counter). Requires all NBLK blocks resident.
__device__ __forceinline__ void gridbar() {
    __syncthreads();
    if (threadIdx.x == 0) {
        __threadfence();
        unsigned gen = d_bgen;
        if (atomicAdd(&d_bcnt, 1u) == NBLK - 1) {
            d_bcnt = 0;
            __threadfence();
            d_bgen = gen + 1u;
        } else {
            while (d_bgen == gen) __nanosleep(64);
        }
        __threadfence();
    }
    __syncthreads();
}

// ---------------- init ----------------
__global__ void k_init(const void* ei) {
    int i = blockIdx.x * blockDim.x + threadIdx.x;
    if (i < NMD) { d_ssum[i] = 0.f; d_menc[i] = 0x007FFFFFu; }
    if (i < D)   { d_gacc[i] = 0.f; d_h[i] = 0.f; d_c[i] = 0.f; }
    if (i == 0) {
        const int* p = (const int*)ei;
        int all0 = 1;
        for (int j = 1; j < 201; j += 2) all0 &= (p[j] == 0);
        d_is64 = all0;
        for (int j = 0; j < HOR; j++) {
            uint2 r = tf2x32(0u, 42u, 0u, (unsigned)j);
            d_keys[j] = make_uint2(r.x, r.y);
        }
    }
}

// ---------------- GEMM (f32x2 packed): Y[r][c] = sum_k X[r][k]*W[c][k] ----------------
__global__ void __launch_bounds__(256) k_gemm(const float* __restrict__ X,
                                              const float* __restrict__ W,
                                              float* __restrict__ Y, int rows) {
    extern __shared__ float sm[];
    float* Ws = sm;               // [128][132] : Ws[k][col] = W[col][k]
    float* Xs = sm + 128 * 132;   // [64][132]
    for (int i = threadIdx.x; i < D * D; i += 256) {
        int col = i >> 7, k = i & 127;
        Ws[k * 132 + col] = W[i];
    }
    __syncthreads();
    int tx = threadIdx.x & 31, ty = threadIdx.x >> 5;
    int row0 = blockIdx.x << 6;
    int nr = rows - row0; if (nr > 64) nr = 64;
    for (int i = threadIdx.x * 4; i < 64 * D; i += 1024) {
        int r = i >> 7, c = i & 127;
        float4 v = make_float4(0.f, 0.f, 0.f, 0.f);
        if (r < nr) v = *(const float4*)(X + (size_t)(row0 + r) * D + c);
        *(float4*)(Xs + r * 132 + c) = v;
    }
    __syncthreads();
    unsigned long long acc[8][2];
#pragma unroll
    for (int ri = 0; ri < 8; ri++) { acc[ri][0] = 0ull; acc[ri][1] = 0ull; }
#pragma unroll 2
    for (int k = 0; k < D; k += 4) {
        ulonglong2 B0 = *(const ulonglong2*)(Ws + (k + 0) * 132 + tx * 4);
        ulonglong2 B1 = *(const ulonglong2*)(Ws + (k + 1) * 132 + tx * 4);
        ulonglong2 B2 = *(const ulonglong2*)(Ws + (k + 2) * 132 + tx * 4);
        ulonglong2 B3 = *(const ulonglong2*)(Ws + (k + 3) * 132 + tx * 4);
#pragma unroll
        for (int ri = 0; ri < 8; ri++) {
            float4 a = *(const float4*)(Xs + (ty * 8 + ri) * 132 + k);
            unsigned long long t;
            t = pk2(a.x); acc[ri][0] = ffma2(t, B0.x, acc[ri][0]); acc[ri][1] = ffma2(t, B0.y, acc[ri][1]);
            t = pk2(a.y); acc[ri][0] = ffma2(t, B1.x, acc[ri][0]); acc[ri][1] = ffma2(t, B1.y, acc[ri][1]);
            t = pk2(a.z); acc[ri][0] = ffma2(t, B2.x, acc[ri][0]); acc[ri][1] = ffma2(t, B2.y, acc[ri][1]);
            t = pk2(a.w); acc[ri][0] = ffma2(t, B3.x, acc[ri][0]); acc[ri][1] = ffma2(t, B3.y, acc[ri][1]);
        }
    }
#pragma unroll
    for (int ri = 0; ri < 8; ri++) {
        int r = row0 + ty * 8 + ri;
        if (r < rows) {
            float2 lo = upk2(acc[ri][0]);
            float2 hi = upk2(acc[ri][1]);
            *(float4*)(Y + (size_t)r * D + tx * 4) = make_float4(lo.x, lo.y, hi.x, hi.y);
        }
    }
}

// ---------------- edge pass 1 (vectorized, 2 edges/warp iter) ----------------
__global__ void __launch_bounds__(256) k_edge1(const void* __restrict__ ei,
                                               const float* __restrict__ att) {
    int lane = threadIdx.x & 31;
    int wid = (blockIdx.x * blockDim.x + threadIdx.x) >> 5;
    int nw = (gridDim.x * blockDim.x) >> 5;
    int is64 = d_is64;
    float4 av = ((const float4*)att)[lane];
    for (int e = wid * 2; e < EE; e += nw * 2) {
        int s1 = eidx(ei, is64, e);
        int dd1 = eidx(ei, is64, (long long)EE + e);
        int s2 = eidx(ei, is64, e + 1);
        int dd2 = eidx(ei, is64, (long long)EE + e + 1);
        float4 l1 = ((const float4*)(d_xl + (size_t)s1 * D))[lane];
        float4 r1 = ((const float4*)(d_xr + (size_t)dd1 * D))[lane];
        float4 l2 = ((const float4*)(d_xl + (size_t)s2 * D))[lane];
        float4 r2 = ((const float4*)(d_xr + (size_t)dd2 * D))[lane];
        float zx, zy, zz, zw, p1, p2;
        zx = l1.x + r1.x; zy = l1.y + r1.y; zz = l1.z + r1.z; zw = l1.w + r1.w;
        zx = zx > 0.f ? zx : NEG * zx; zy = zy > 0.f ? zy : NEG * zy;
        zz = zz > 0.f ? zz : NEG * zz; zw = zw > 0.f ? zw : NEG * zw;
        p1 = av.x * zx + av.y * zy + av.z * zz + av.w * zw;
        zx = l2.x + r2.x; zy = l2.y + r2.y; zz = l2.z + r2.z; zw = l2.w + r2.w;
        zx = zx > 0.f ? zx : NEG * zx; zy = zy > 0.f ? zy : NEG * zy;
        zz = zz > 0.f ? zz : NEG * zz; zw = zw > 0.f ? zw : NEG * zw;
        p2 = av.x * zx + av.y * zy + av.z * zz + av.w * zw;
#pragma unroll
        for (int o = 16; o; o >>= 1) {
            p1 += __shfl_xor_sync(~0u, p1, o);
            p2 += __shfl_xor_sync(~0u, p2, o);
        }
        if (lane == 0) {
            d_ew[e] = p1;     atomicMax(&d_menc[dd1], encf(p1));
            d_ew[e + 1] = p2; atomicMax(&d_menc[dd2], encf(p2));
        }
    }
}

// ---------------- edge pass 2 ----------------
__global__ void k_edge2(const void* __restrict__ ei) {
    int i = blockIdx.x * blockDim.x + threadIdx.x;
    if (i >= EE) return;
    int is64 = d_is64;
    int dst = eidx(ei, is64, (long long)EE + i);
    float m = decf(d_menc[dst]);
    float ex = expf(d_ew[i] - m);
    d_ew[i] = ex;
    atomicAdd(&d_ssum[dst], ex);
}

// ---------------- edge pass 3 ----------------
__global__ void k_edge3(const void* __restrict__ ei) {
    __shared__ float sg[D];
    int lane = threadIdx.x & 31;
    if (threadIdx.x < D) sg[threadIdx.x] = 0.f;
    __syncthreads();
    int wid = (blockIdx.x * blockDim.x + threadIdx.x) >> 5;
    int nw = (gridDim.x * blockDim.x) >> 5;
    int is64 = d_is64;
    float4 acc = make_float4(0.f, 0.f, 0.f, 0.f);
    const int nbatch = EE / 32;
    for (int b = wid; b < nbatch; b += nw) {
        int e = b * 32 + lane;
        int src = eidx(ei, is64, e);
        int dst = eidx(ei, is64, (long long)EE + e);
        float w = d_ew[e] / d_ssum[dst];
#pragma unroll
        for (int t = 0; t < 32; t++) {
            int bs = __shfl_sync(~0u, src, t);
            float bw = __shfl_sync(~0u, w, t);
            float4 v = *(const float4*)(d_xl + (size_t)bs * D + lane * 4);
            acc.x += bw * v.x; acc.y += bw * v.y; acc.z += bw * v.z; acc.w += bw * v.w;
        }
    }
    atomicAdd(&sg[lane * 4 + 0], acc.x);
    atomicAdd(&sg[lane * 4 + 1], acc.y);
    atomicAdd(&sg[lane * 4 + 2], acc.z);
    atomicAdd(&sg[lane * 4 + 3], acc.w);
    __syncthreads();
    if (threadIdx.x < D) atomicAdd(&d_gacc[threadIdx.x], sg[threadIdx.x]);
}

// ---------------- finalize pooled g -> d_inp ----------------
__global__ void k_fing(const float* __restrict__ conv_bias) {
    int t = threadIdx.x;
    if (t < D) d_inp[t] = d_gacc[t] * (1.0f / (float)NMD) + conv_bias[t];
}

// ---------------- persistent rollout: 8 steps, grid barriers ----------------
__global__ void __launch_bounds__(256) k_rollout(
    const float* __restrict__ Wih, const float* __restrict__ Whh,
    const float* __restrict__ bih, const float* __restrict__ bhh,
    const float* __restrict__ W1,  const float* __restrict__ b1,
    const float* __restrict__ W2,  const float* __restrict__ b2,
    const float* __restrict__ emb, float* __restrict__ out) {
    __shared__ float sh_h[D];
    __shared__ float wbest[8]; __shared__ int wbi[8];
    __shared__ float wlm[8], wls[8];
    __shared__ int sAct;
    int t = threadIdx.x, lane = t & 31, w = t >> 5;
    const float NI = neginf();

    for (int s = 0; s < HOR; s++) {
        // ---- P1: LSTM gates, distributed (512 rows over NBLK*8 warps) ----
        int gw = blockIdx.x * 8 + w;
        if (gw < 4 * D) {
            int r = gw;
            float4 wa = ((const float4*)(Wih + (size_t)r * D))[lane];
            float4 wb = ((const float4*)(Whh + (size_t)r * D))[lane];
            float4 iv = ((const float4*)d_inp)[lane];
            float4 hv = ((const float4*)d_h)[lane];
            float p = wa.x * iv.x + wa.y * iv.y + wa.z * iv.z + wa.w * iv.w
                    + wb.x * hv.x + wb.y * hv.y + wb.z * hv.z + wb.w * hv.w;
#pragma unroll
            for (int o = 16; o; o >>= 1) p += __shfl_xor_sync(~0u, p, o);
            if (lane == 0) d_gates[r] = p + bih[r] + bhh[r];
        }
        gridbar();
        // ---- P2: block 0: nonlinearity + c/h update + pred layer 1 ----
        if (blockIdx.x == 0) {
            if (t < D) {
                float ig = 1.f / (1.f + expf(-d_gates[t]));
                float fg = 1.f / (1.f + expf(-d_gates[D + t]));
                float gg = tanhf(d_gates[2 * D + t]);
                float og = 1.f / (1.f + expf(-d_gates[3 * D + t]));
                float c = fg * d_c[t] + ig * gg;
                float h = og * tanhf(c);
                d_c[t] = c; d_h[t] = h; sh_h[t] = h;
                if (s == HOR - 1) { out[2 * HOR + t] = h; out[2 * HOR + D + t] = c; }
            }
            __syncthreads();
            float4 hv = ((const float4*)sh_h)[lane];
            for (int r = w; r < D; r += 8) {
                float4 wv = ((const float4*)(W1 + (size_t)r * D))[lane];
                float p = wv.x * hv.x + wv.y * hv.y + wv.z * hv.z + wv.w * hv.w;
#pragma unroll
                for (int o = 16; o; o >>= 1) p += __shfl_xor_sync(~0u, p, o);
                if (lane == 0) { p += b1[r]; d_h2[r] = p > 0.f ? p : 0.f; }
            }
        }
        gridbar();
        // ---- P3: logits + gumbel + online softmax (all blocks) ----
        {
            uint2 key = d_keys[s];
            float4 h0 = ((const float4*)d_h2)[lane];
            int nwarp = NBLK * 8;
            float best = NI; int bi = 0; float lm = NI, ls = 0.f;
            for (int base = gw * 32; base < NMD; base += nwarp * 32) {
                int myrow = base + lane;
                float myl = 0.f;
                float myb2 = (myrow < NMD) ? b2[myrow] : 0.f;
                int jmax = NMD - base; if (jmax > 32) jmax = 32;
                for (int j = 0; j < jmax; j++) {
                    int r = base + j;
                    float4 wv = ((const float4*)(W2 + (size_t)r * D))[lane];
                    float p = wv.x * h0.x + wv.y * h0.y + wv.z * h0.z + wv.w * h0.w;
#pragma unroll
                    for (int o = 16; o; o >>= 1) p += __shfl_xor_sync(~0u, p, o);
                    if (lane == j) myl = p + myb2;
                }
                float score, cm, cs; int sidx = myrow;
                if (myrow < NMD) {
                    d_logits[myrow] = myl;
                    uint2 tr = tf2x32(key.x, key.y, 0u, (unsigned)myrow);
                    unsigned bits = tr.x ^ tr.y;
                    float u = __uint_as_float((bits >> 9) | 0x3f800000u) - 1.0f;
                    if (u == 0.f) u = 1.17549435e-38f;
                    score = myl - logf(-logf(u));
                    cm = myl; cs = 1.f;
                } else { score = NI; cm = NI; cs = 0.f; }
#pragma unroll
                for (int o = 16; o; o >>= 1) {
                    float os = __shfl_xor_sync(~0u, score, o);
                    int oi = __shfl_xor_sync(~0u, sidx, o);
                    if (os > score || (os == score && oi < sidx)) { score = os; sidx = oi; }
                    float om = __shfl_xor_sync(~0u, cm, o);
                    float ou = __shfl_xor_sync(~0u, cs, o);
                    if (ou > 0.f) {
                        if (om > cm) { cs = cs * expf(cm - om) + ou; cm = om; }
                        else         { cs += ou * expf(om - cm); }
                    }
                }
                if (score > best || (score == best && sidx < bi)) { best = score; bi = sidx; }
                if (cs > 0.f) {
                    if (cm > lm) { ls = ls * expf(lm - cm) + cs; lm = cm; }
                    else         { ls += cs * expf(cm - lm); }
                }
            }
            if (lane == 0) { wbest[w] = best; wbi[w] = bi; wlm[w] = lm; wls[w] = ls; }
            __syncthreads();
            if (t == 0) {
                float B = NI; int BI = 0; float M = NI, S = 0.f;
                for (int i = 0; i < 8; i++) {
                    if (wbest[i] > B || (wbest[i] == B && wbi[i] < BI)) { B = wbest[i]; BI = wbi[i]; }
                    if (wls[i] > 0.f) {
                        if (wlm[i] > M) { S = S * expf(M - wlm[i]) + wls[i]; M = wlm[i]; }
                        else            { S += wls[i] * expf(wlm[i] - M); }
                    }
                }
                d_pm_best[blockIdx.x] = B; d_pm_bi[blockIdx.x] = BI;
                d_pm_lm[blockIdx.x] = M;  d_pm_ls[blockIdx.x] = S;
            }
        }
        gridbar();
        // ---- P4: block 0: reduce partials, sample, fetch embedding ----
        if (blockIdx.x == 0) {
            if (t == 0) {
                float B = NI; int BI = 0; float M = NI, S = 0.f;
                for (int i = 0; i < NBLK; i++) {
                    float b = d_pm_best[i]; int bidx = d_pm_bi[i];
                    if (b > B || (b == B && bidx < BI)) { B = b; BI = bidx; }
                    float m = d_pm_lm[i], sv = d_pm_ls[i];
                    if (sv > 0.f) {
                        if (m > M) { S = S * expf(M - m) + sv; M = m; }
                        else       { S += sv * expf(m - M); }
                    }
                }
                out[s] = (float)BI;
                out[HOR + s] = d_logits[BI] - (M + logf(S));
                sAct = BI;
            }
            __syncthreads();
            int a = sAct;
            if (t < D) d_inp[t] = emb[(size_t)a * D + t];
        }
        gridbar();
    }
}

// ---------------- launch ----------------
extern "C" void kernel_launch(void* const* d_in, const int* in_sizes, int n_in,
                              void* d_out, int out_size) {
    const float* state_features = (const float*)d_in[0];
    const float* model_features = (const float*)d_in[1];
    const void*  edge_index     = d_in[2];
    const float* W_l   = (const float*)d_in[3];
    const float* W_r   = (const float*)d_in[4];
    const float* att   = (const float*)d_in[5];
    const float* cbias = (const float*)d_in[6];
    const float* Wih   = (const float*)d_in[7];
    const float* Whh   = (const float*)d_in[8];
    const float* bih   = (const float*)d_in[9];
    const float* bhh   = (const float*)d_in[10];
    const float* W1    = (const float*)d_in[11];
    const float* b1    = (const float*)d_in[12];
    const float* W2    = (const float*)d_in[13];
    const float* b2    = (const float*)d_in[14];
    const float* emb   = (const float*)d_in[15];
    float* out = (float*)d_out;

    const int smem = (128 * 132 + 64 * 132) * (int)sizeof(float);  // 101376
    cudaFuncSetAttribute(k_gemm, cudaFuncAttributeMaxDynamicSharedMemorySize, smem);

    float* xl = nullptr; float* xr = nullptr;
    cudaGetSymbolAddress((void**)&xl, d_xl);
    cudaGetSymbolAddress((void**)&xr, d_xr);

    k_init<<<(NMD + 255) / 256, 256>>>(edge_index);
    k_gemm<<<(NSN + 63) / 64, 256, smem>>>(state_features, W_l, xl, NSN);
    k_gemm<<<(NMD + 63) / 64, 256, smem>>>(model_features, W_r, xr, NMD);
    k_edge1<<<592, 256>>>(edge_index, att);
    k_edge2<<<(EE + 255) / 256, 256>>>(edge_index);
    k_edge3<<<592, 256>>>(edge_index);
    k_fing<<<1, 128>>>(cbias);
    k_rollout<<<NBLK, 256>>>(Wih, Whh, bih, bhh, W1, b1, W2, b2, emb, out);
    (void)in_sizes; (void)n_in; (void)out_size;
}

// round 5
// speedup vs baseline: 1.2027x; 1.2027x over previous
#include <cuda_runtime.h>
#include <cstdint>
#include <cstddef>

#define NSN  100000
#define NMD  50000
#define EE   600000
#define D    128
#define HOR  8
#define NEG  0.2f
#define GLOG 256   // blocks for k_logits

// ---------------- device scratch ----------------
__device__ float    d_xl[(size_t)NSN * D];
__device__ float    d_xr[(size_t)NMD * D];
__device__ float    d_ew[EE];                  // exp(e) per edge
__device__ float    d_ssum[NMD];               // segment sum of exp
__device__ float    d_csrc[NSN];               // per-src scalar weight
__device__ __align__(16) float d_gacc[D];
__device__ __align__(16) float d_inp[D];
__device__ __align__(16) float d_h[D];
__device__ __align__(16) float d_c[D];
__device__ __align__(16) float d_h2[D];
__device__ float    d_logits[NMD];
__device__ float    d_pm_best[GLOG];
__device__ int      d_pm_bi[GLOG];
__device__ float    d_pm_lm[GLOG];
__device__ float    d_pm_ls[GLOG];
__device__ uint2    d_keys[HOR];
__device__ int      d_is64;

// ---------------- helpers ----------------
__device__ __forceinline__ int eidx(const void* ei, int is64, long long pos) {
    return is64 ? (int)((const long long*)ei)[pos] : ((const int*)ei)[pos];
}
__device__ __forceinline__ float neginf() { return __int_as_float((int)0xff800000); }

// packed f32x2 FMA (PTX-only FFMA2: 2 fp32 FMA per fma-pipe slot)
__device__ __forceinline__ unsigned long long pk2(float x) {
    unsigned long long r; asm("mov.b64 %0, {%1, %1};" : "=l"(r) : "f"(x)); return r;
}
__device__ __forceinline__ unsigned long long ffma2(unsigned long long a,
                                                   unsigned long long b,
                                                   unsigned long long c) {
    unsigned long long d_;
    asm("fma.rn.f32x2 %0, %1, %2, %3;" : "=l"(d_) : "l"(a), "l"(b), "l"(c));
    return d_;
}
__device__ __forceinline__ float2 upk2(unsigned long long v) {
    float lo, hi; asm("mov.b64 {%0, %1}, %2;" : "=f"(lo), "=f"(hi) : "l"(v));
    return make_float2(lo, hi);
}

// JAX threefry2x32, 20 rounds
__device__ __forceinline__ uint2 tf2x32(unsigned k0, unsigned k1, unsigned x0, unsigned x1) {
    unsigned k2 = k0 ^ k1 ^ 0x1BD11BDAu;
    x0 += k0; x1 += k1;
#define TFR(r) { x0 += x1; x1 = (x1 << (r)) | (x1 >> (32 - (r))); x1 ^= x0; }
    TFR(13) TFR(15) TFR(26) TFR(6)   x0 += k1; x1 += k2 + 1u;
    TFR(17) TFR(29) TFR(16) TFR(24)  x0 += k2; x1 += k0 + 2u;
    TFR(13) TFR(15) TFR(26) TFR(6)   x0 += k0; x1 += k1 + 3u;
    TFR(17) TFR(29) TFR(16) TFR(24)  x0 += k1; x1 += k2 + 4u;
    TFR(13) TFR(15) TFR(26) TFR(6)   x0 += k2; x1 += k0 + 5u;
#undef TFR
    return make_uint2(x0, x1);
}

// ---------------- init ----------------
__global__ void k_init(const void* ei) {
    int i = blockIdx.x * blockDim.x + threadIdx.x;
    if (i < NMD) d_ssum[i] = 0.f;
    if (i < NSN) d_csrc[i] = 0.f;
    if (i < D)   { d_gacc[i] = 0.f; d_h[i] = 0.f; d_c[i] = 0.f; }
    if (i == 0) {
        const int* p = (const int*)ei;
        int all0 = 1;
        for (int j = 1; j < 201; j += 2) all0 &= (p[j] == 0);
        d_is64 = all0;
        // partitionable threefry split(key(42), 8): keys[j] = tf(k, (0, j))
        for (int j = 0; j < HOR; j++) {
            uint2 r = tf2x32(0u, 42u, 0u, (unsigned)j);
            d_keys[j] = make_uint2(r.x, r.y);
        }
    }
}

// ---------------- GEMM (f32x2 packed): Y[r][c] = sum_k X[r][k]*W[c][k] ----------------
__global__ void __launch_bounds__(256) k_gemm(const float* __restrict__ X,
                                              const float* __restrict__ W,
                                              float* __restrict__ Y, int rows) {
    extern __shared__ float sm[];
    float* Ws = sm;               // [128][132] : Ws[k][col] = W[col][k]
    float* Xs = sm + 128 * 132;   // [64][132]
    for (int i = threadIdx.x; i < D * D; i += 256) {
        int col = i >> 7, k = i & 127;
        Ws[k * 132 + col] = W[i];
    }
    __syncthreads();
    int tx = threadIdx.x & 31, ty = threadIdx.x >> 5;
    int row0 = blockIdx.x << 6;
    int nr = rows - row0; if (nr > 64) nr = 64;
    for (int i = threadIdx.x * 4; i < 64 * D; i += 1024) {
        int r = i >> 7, c = i & 127;
        float4 v = make_float4(0.f, 0.f, 0.f, 0.f);
        if (r < nr) v = *(const float4*)(X + (size_t)(row0 + r) * D + c);
        *(float4*)(Xs + r * 132 + c) = v;
    }
    __syncthreads();
    unsigned long long acc[8][2];
#pragma unroll
    for (int ri = 0; ri < 8; ri++) { acc[ri][0] = 0ull; acc[ri][1] = 0ull; }
#pragma unroll 2
    for (int k = 0; k < D; k += 4) {
        ulonglong2 B0 = *(const ulonglong2*)(Ws + (k + 0) * 132 + tx * 4);
        ulonglong2 B1 = *(const ulonglong2*)(Ws + (k + 1) * 132 + tx * 4);
        ulonglong2 B2 = *(const ulonglong2*)(Ws + (k + 2) * 132 + tx * 4);
        ulonglong2 B3 = *(const ulonglong2*)(Ws + (k + 3) * 132 + tx * 4);
#pragma unroll
        for (int ri = 0; ri < 8; ri++) {
            float4 a = *(const float4*)(Xs + (ty * 8 + ri) * 132 + k);
            unsigned long long t;
            t = pk2(a.x); acc[ri][0] = ffma2(t, B0.x, acc[ri][0]); acc[ri][1] = ffma2(t, B0.y, acc[ri][1]);
            t = pk2(a.y); acc[ri][0] = ffma2(t, B1.x, acc[ri][0]); acc[ri][1] = ffma2(t, B1.y, acc[ri][1]);
            t = pk2(a.z); acc[ri][0] = ffma2(t, B2.x, acc[ri][0]); acc[ri][1] = ffma2(t, B2.y, acc[ri][1]);
            t = pk2(a.w); acc[ri][0] = ffma2(t, B3.x, acc[ri][0]); acc[ri][1] = ffma2(t, B3.y, acc[ri][1]);
        }
    }
#pragma unroll
    for (int ri = 0; ri < 8; ri++) {
        int r = row0 + ty * 8 + ri;
        if (r < rows) {
            float2 lo = upk2(acc[ri][0]);
            float2 hi = upk2(acc[ri][1]);
            *(float4*)(Y + (size_t)r * D + tx * 4) = make_float4(lo.x, lo.y, hi.x, hi.y);
        }
    }
}

// ---------------- fused edge pass: ex = exp(att.lrelu(xl[src]+xr[dst])); segsum ----------------
// (no max-subtraction: e std ~1, max over 600k ~5 -> exp safe in fp32; alpha identical)
__global__ void __launch_bounds__(256) k_edge12(const void* __restrict__ ei,
                                                const float* __restrict__ att) {
    int lane = threadIdx.x & 31;
    int wid = (blockIdx.x * blockDim.x + threadIdx.x) >> 5;
    int nw = (gridDim.x * blockDim.x) >> 5;
    int is64 = d_is64;
    float4 av = ((const float4*)att)[lane];
    for (int e = wid * 2; e < EE; e += nw * 2) {
        int s1 = eidx(ei, is64, e);
        int dd1 = eidx(ei, is64, (long long)EE + e);
        int s2 = eidx(ei, is64, e + 1);
        int dd2 = eidx(ei, is64, (long long)EE + e + 1);
        float4 l1 = ((const float4*)(d_xl + (size_t)s1 * D))[lane];
        float4 r1 = ((const float4*)(d_xr + (size_t)dd1 * D))[lane];
        float4 l2 = ((const float4*)(d_xl + (size_t)s2 * D))[lane];
        float4 r2 = ((const float4*)(d_xr + (size_t)dd2 * D))[lane];
        float zx, zy, zz, zw, p1, p2;
        zx = l1.x + r1.x; zy = l1.y + r1.y; zz = l1.z + r1.z; zw = l1.w + r1.w;
        zx = zx > 0.f ? zx : NEG * zx; zy = zy > 0.f ? zy : NEG * zy;
        zz = zz > 0.f ? zz : NEG * zz; zw = zw > 0.f ? zw : NEG * zw;
        p1 = av.x * zx + av.y * zy + av.z * zz + av.w * zw;
        zx = l2.x + r2.x; zy = l2.y + r2.y; zz = l2.z + r2.z; zw = l2.w + r2.w;
        zx = zx > 0.f ? zx : NEG * zx; zy = zy > 0.f ? zy : NEG * zy;
        zz = zz > 0.f ? zz : NEG * zz; zw = zw > 0.f ? zw : NEG * zw;
        p2 = av.x * zx + av.y * zy + av.z * zz + av.w * zw;
#pragma unroll
        for (int o = 16; o; o >>= 1) {
            p1 += __shfl_xor_sync(~0u, p1, o);
            p2 += __shfl_xor_sync(~0u, p2, o);
        }
        if (lane == 0) {
            float e1 = expf(p1), e2 = expf(p2);
            d_ew[e] = e1;     atomicAdd(&d_ssum[dd1], e1);
            d_ew[e + 1] = e2; atomicAdd(&d_ssum[dd2], e2);
        }
    }
}

// ---------------- edge pass 3a (scalar): c[src] += ew[e]/ssum[dst] ----------------
__global__ void k_edge3a(const void* __restrict__ ei) {
    int i = blockIdx.x * blockDim.x + threadIdx.x;
    if (i >= EE) return;
    int is64 = d_is64;
    int src = eidx(ei, is64, i);
    int dst = eidx(ei, is64, (long long)EE + i);
    float w = d_ew[i] / d_ssum[dst];
    atomicAdd(&d_csrc[src], w);
}

// ---------------- dense pass: g += c[r] * xl[r] (coalesced 51MB) ----------------
__global__ void __launch_bounds__(256) k_dense() {
    __shared__ float sg[D];
    int lane = threadIdx.x & 31, w = threadIdx.x >> 5;
    if (threadIdx.x < D) sg[threadIdx.x] = 0.f;
    __syncthreads();
    int gw = blockIdx.x * 8 + w;
    int nw = gridDim.x * 8;
    float4 acc = make_float4(0.f, 0.f, 0.f, 0.f);
    for (int r = gw; r < NSN; r += nw) {
        float cv = d_csrc[r];
        float4 v = ((const float4*)(d_xl + (size_t)r * D))[lane];
        acc.x += cv * v.x; acc.y += cv * v.y; acc.z += cv * v.z; acc.w += cv * v.w;
    }
    atomicAdd(&sg[lane * 4 + 0], acc.x);
    atomicAdd(&sg[lane * 4 + 1], acc.y);
    atomicAdd(&sg[lane * 4 + 2], acc.z);
    atomicAdd(&sg[lane * 4 + 3], acc.w);
    __syncthreads();
    if (threadIdx.x < D) atomicAdd(&d_gacc[threadIdx.x], sg[threadIdx.x]);
}

// ---------------- finalize pooled g -> d_inp ----------------
__global__ void k_fing(const float* __restrict__ conv_bias) {
    int t = threadIdx.x;
    if (t < D) d_inp[t] = d_gacc[t] * (1.0f / (float)NMD) + conv_bias[t];
}

// ---------------- LSTM cell + pred layer1 (1 block, 512 threads) ----------------
__global__ void __launch_bounds__(512) k_lstm(
    const float* __restrict__ Wih, const float* __restrict__ Whh,
    const float* __restrict__ bih, const float* __restrict__ bhh,
    const float* __restrict__ W1,  const float* __restrict__ b1,
    float* __restrict__ out) {
    __shared__ float si[D], sh[D], sg[4 * D], snh[D];
    int t = threadIdx.x;
    if (t < D) { si[t] = d_inp[t]; sh[t] = d_h[t]; }
    __syncthreads();
    float acc = bih[t] + bhh[t];
    const float4* wi = (const float4*)(Wih + (size_t)t * D);
    const float4* wh = (const float4*)(Whh + (size_t)t * D);
#pragma unroll 8
    for (int k = 0; k < 32; k++) {
        float4 a = wi[k]; float4 b = wh[k];
        float4 iv = *(const float4*)(si + 4 * k);
        float4 hv = *(const float4*)(sh + 4 * k);
        acc += a.x * iv.x + a.y * iv.y + a.z * iv.z + a.w * iv.w;
        acc += b.x * hv.x + b.y * hv.y + b.z * hv.z + b.w * hv.w;
    }
    sg[t] = acc;
    __syncthreads();
    if (t < D) {
        float ig = 1.f / (1.f + expf(-sg[t]));
        float fg = 1.f / (1.f + expf(-sg[D + t]));
        float gg = tanhf(sg[2 * D + t]);
        float og = 1.f / (1.f + expf(-sg[3 * D + t]));
        float c = fg * d_c[t] + ig * gg;
        float h = og * tanhf(c);
        d_c[t] = c; d_h[t] = h;
        snh[t] = h;
        out[2 * HOR + t] = h;
        out[2 * HOR + D + t] = c;
    }
    __syncthreads();
    if (t < D) {
        float a2 = b1[t];
        const float4* w1 = (const float4*)(W1 + (size_t)t * D);
#pragma unroll 8
        for (int k = 0; k < 32; k++) {
            float4 a = w1[k];
            float4 hv = *(const float4*)(snh + 4 * k);
            a2 += a.x * hv.x + a.y * hv.y + a.z * hv.z + a.w * hv.w;
        }
        d_h2[t] = a2 > 0.f ? a2 : 0.f;
    }
}

// ---------------- logits + gumbel + online softmax partials ----------------
__global__ void __launch_bounds__(256) k_logits(const float* __restrict__ W2,
                                                const float* __restrict__ b2, int step) {
    __shared__ float sh2[D];
    __shared__ float wbest[8]; __shared__ int wbi[8];
    __shared__ float wlm[8], wls[8];
    int t = threadIdx.x, lane = t & 31, w = t >> 5;
    if (t < D) sh2[t] = d_h2[t];
    __syncthreads();
    uint2 key = d_keys[step];
    float4 h0 = *(const float4*)(sh2 + lane * 4);
    int wid = (blockIdx.x * blockDim.x + t) >> 5;
    int nw = (gridDim.x * blockDim.x) >> 5;
    float best = neginf();
    int bi = 0;
    float lm = best, ls = 0.f;
    for (int r = wid; r < NMD; r += nw) {
        float4 wv = *(const float4*)(W2 + (size_t)r * D + lane * 4);
        float p = wv.x * h0.x + wv.y * h0.y + wv.z * h0.z + wv.w * h0.w;
#pragma unroll
        for (int o = 16; o; o >>= 1) p += __shfl_xor_sync(~0u, p, o);
        if (lane == 0) {
            float l = p + b2[r];
            d_logits[r] = l;
            uint2 tr = tf2x32(key.x, key.y, 0u, (unsigned)r);
            unsigned bits = tr.x ^ tr.y;
            float u = __uint_as_float((bits >> 9) | 0x3f800000u) - 1.0f;
            if (u == 0.f) u = 1.17549435e-38f;
            float gum = -logf(-logf(u));
            float sc = gum + l;
            if (sc > best) { best = sc; bi = r; }
            if (l > lm) { ls = ls * expf(lm - l) + 1.f; lm = l; }
            else        { ls += expf(l - lm); }
        }
    }
    if (lane == 0) { wbest[w] = best; wbi[w] = bi; wlm[w] = lm; wls[w] = ls; }
    __syncthreads();
    if (t == 0) {
        float B = neginf(); int BI = 0;
        float M = B, S = 0.f;
        for (int i = 0; i < 8; i++) {
            if (wbest[i] > B || (wbest[i] == B && wbi[i] < BI)) { B = wbest[i]; BI = wbi[i]; }
            if (wls[i] > 0.f) {
                if (wlm[i] > M) { S = S * expf(M - wlm[i]) + wls[i]; M = wlm[i]; }
                else            { S += wls[i] * expf(wlm[i] - M); }
            }
        }
        d_pm_best[blockIdx.x] = B; d_pm_bi[blockIdx.x] = BI;
        d_pm_lm[blockIdx.x] = M;  d_pm_ls[blockIdx.x] = S;
    }
}

// ---------------- reduce partials, sample, fetch embedding ----------------
__global__ void k_sample(const float* __restrict__ emb, float* __restrict__ out, int step) {
    __shared__ int sA;
    int t = threadIdx.x;
    if (t == 0) {
        float B = neginf(); int BI = 0;
        float M = B, S = 0.f;
        for (int i = 0; i < GLOG; i++) {
            float b = d_pm_best[i]; int bidx = d_pm_bi[i];
            if (b > B || (b == B && bidx < BI)) { B = b; BI = bidx; }
            float m = d_pm_lm[i], s = d_pm_ls[i];
            if (s > 0.f) {
                if (m > M) { S = S * expf(M - m) + s; M = m; }
                else       { S += s * expf(m - M); }
            }
        }
        float lp = d_logits[BI] - (M + logf(S));
        out[step] = (float)BI;
        out[HOR + step] = lp;
        sA = BI;
    }
    __syncthreads();
    int a = sA;
    if (t < D) d_inp[t] = emb[(size_t)a * D + t];
}

// ---------------- launch ----------------
extern "C" void kernel_launch(void* const* d_in, const int* in_sizes, int n_in,
                              void* d_out, int out_size) {
    const float* state_features = (const float*)d_in[0];
    const float* model_features = (const float*)d_in[1];
    const void*  edge_index     = d_in[2];
    const float* W_l   = (const float*)d_in[3];
    const float* W_r   = (const float*)d_in[4];
    const float* att   = (const float*)d_in[5];
    const float* cbias = (const float*)d_in[6];
    const float* Wih   = (const float*)d_in[7];
    const float* Whh   = (const float*)d_in[8];
    const float* bih   = (const float*)d_in[9];
    const float* bhh   = (const float*)d_in[10];
    const float* W1    = (const float*)d_in[11];
    const float* b1    = (const float*)d_in[12];
    const float* W2    = (const float*)d_in[13];
    const float* b2    = (const float*)d_in[14];
    const float* emb   = (const float*)d_in[15];
    float* out = (float*)d_out;

    const int smem = (128 * 132 + 64 * 132) * (int)sizeof(float);  // 101376
    cudaFuncSetAttribute(k_gemm, cudaFuncAttributeMaxDynamicSharedMemorySize, smem);

    float* xl = nullptr; float* xr = nullptr;
    cudaGetSymbolAddress((void**)&xl, d_xl);
    cudaGetSymbolAddress((void**)&xr, d_xr);

    k_init<<<(NSN + 255) / 256, 256>>>(edge_index);
    k_gemm<<<(NSN + 63) / 64, 256, smem>>>(state_features, W_l, xl, NSN);
    k_gemm<<<(NMD + 63) / 64, 256, smem>>>(model_features, W_r, xr, NMD);
    k_edge12<<<1184, 256>>>(edge_index, att);
    k_edge3a<<<(EE + 255) / 256, 256>>>(edge_index);
    k_dense<<<296, 256>>>();
    k_fing<<<1, 128>>>(cbias);
    for (int s = 0; s < HOR; s++) {
        k_lstm<<<1, 512>>>(Wih, Whh, bih, bhh, W1, b1, out);
        k_logits<<<GLOG, 256>>>(W2, b2, s);
        k_sample<<<1, 128>>>(emb, out, s);
    }
    (void)in_sizes; (void)n_in; (void)out_size;
}

// round 6
// speedup vs baseline: 1.4351x; 1.1932x over previous
#include <cuda_runtime.h>
#include <cstdint>
#include <cstddef>

#define NSN  100000
#define NMD  50000
#define EE   600000
#define D    128
#define HOR  8
#define NEG  0.2f
#define GLOG 256   // blocks for k_logits

// ---------------- device scratch ----------------
__device__ float    d_xl[(size_t)NSN * D];
__device__ float    d_xr[(size_t)NMD * D];
__device__ float    d_ew[EE];                  // exp(e) per edge
__device__ float    d_ssum[NMD];               // segment sum of exp
__device__ float    d_csrc[NSN];               // per-src scalar weight
__device__ __align__(16) float d_gacc[D];
__device__ __align__(16) float d_inp[D];
__device__ __align__(16) float d_h[D];
__device__ __align__(16) float d_c[D];
__device__ __align__(16) float d_h2[D];
__device__ float    d_logits[NMD];
__device__ float    d_pm_best[GLOG];
__device__ int      d_pm_bi[GLOG];
__device__ float    d_pm_lm[GLOG];
__device__ float    d_pm_ls[GLOG];
__device__ uint2    d_keys[HOR];
__device__ int      d_is64;

// ---------------- helpers ----------------
__device__ __forceinline__ int eidx(const void* ei, int is64, long long pos) {
    return is64 ? (int)((const long long*)ei)[pos] : ((const int*)ei)[pos];
}
__device__ __forceinline__ float neginf() { return __int_as_float((int)0xff800000); }

// packed f32x2 FMA (PTX-only FFMA2: 2 fp32 FMA per fma-pipe slot)
__device__ __forceinline__ unsigned long long pk2(float x) {
    unsigned long long r; asm("mov.b64 %0, {%1, %1};" : "=l"(r) : "f"(x)); return r;
}
__device__ __forceinline__ unsigned long long ffma2(unsigned long long a,
                                                   unsigned long long b,
                                                   unsigned long long c) {
    unsigned long long d_;
    asm("fma.rn.f32x2 %0, %1, %2, %3;" : "=l"(d_) : "l"(a), "l"(b), "l"(c));
    return d_;
}
__device__ __forceinline__ float2 upk2(unsigned long long v) {
    float lo, hi; asm("mov.b64 {%0, %1}, %2;" : "=f"(lo), "=f"(hi) : "l"(v));
    return make_float2(lo, hi);
}

// JAX threefry2x32, 20 rounds
__device__ __forceinline__ uint2 tf2x32(unsigned k0, unsigned k1, unsigned x0, unsigned x1) {
    unsigned k2 = k0 ^ k1 ^ 0x1BD11BDAu;
    x0 += k0; x1 += k1;
#define TFR(r) { x0 += x1; x1 = (x1 << (r)) | (x1 >> (32 - (r))); x1 ^= x0; }
    TFR(13) TFR(15) TFR(26) TFR(6)   x0 += k1; x1 += k2 + 1u;
    TFR(17) TFR(29) TFR(16) TFR(24)  x0 += k2; x1 += k0 + 2u;
    TFR(13) TFR(15) TFR(26) TFR(6)   x0 += k0; x1 += k1 + 3u;
    TFR(17) TFR(29) TFR(16) TFR(24)  x0 += k1; x1 += k2 + 4u;
    TFR(13) TFR(15) TFR(26) TFR(6)   x0 += k2; x1 += k0 + 5u;
#undef TFR
    return make_uint2(x0, x1);
}

// merge two (max, sum) online-softmax states
__device__ __forceinline__ void lsmerge(float& M, float& S, float m, float s) {
    if (s > 0.f) {
        if (m > M) { S = S * expf(M - m) + s; M = m; }
        else       { S += s * expf(m - M); }
    }
}

// ---------------- init ----------------
__global__ void k_init(const void* ei) {
    int i = blockIdx.x * blockDim.x + threadIdx.x;
    if (i < NMD) d_ssum[i] = 0.f;
    if (i < NSN) d_csrc[i] = 0.f;
    if (i < D)   { d_gacc[i] = 0.f; d_h[i] = 0.f; d_c[i] = 0.f; }
    if (i == 0) {
        const int* p = (const int*)ei;
        int all0 = 1;
        for (int j = 1; j < 201; j += 2) all0 &= (p[j] == 0);
        d_is64 = all0;
        for (int j = 0; j < HOR; j++) {
            uint2 r = tf2x32(0u, 42u, 0u, (unsigned)j);
            d_keys[j] = make_uint2(r.x, r.y);
        }
    }
}

__global__ void k_nop() {}

// ---------------- GEMM2: 128x128 tile, thread=8x8 outputs, f32x2 packed ----------------
__global__ void __launch_bounds__(256) k_gemm2(const float* __restrict__ X,
                                               const float* __restrict__ W,
                                               float* __restrict__ Y, int rows) {
    extern __shared__ float sm[];
    float* Ws = sm;                 // [128][132] : Ws[k][col] = W[col][k]
    float* Xs = sm + 128 * 132;     // [128][132]
    for (int i = threadIdx.x; i < D * D; i += 256) {
        int col = i >> 7, k = i & 127;
        Ws[k * 132 + col] = W[i];
    }
    int row0 = blockIdx.x << 7;
    int nr = rows - row0; if (nr > 128) nr = 128;
    for (int i = threadIdx.x * 4; i < 128 * D; i += 1024) {
        int r = i >> 7, c = i & 127;
        float4 v = make_float4(0.f, 0.f, 0.f, 0.f);
        if (r < nr) v = *(const float4*)(X + (size_t)(row0 + r) * D + c);
        *(float4*)(Xs + r * 132 + c) = v;
    }
    __syncthreads();
    int tx = threadIdx.x & 15, ty = threadIdx.x >> 4;  // cols tx*8.., rows ty*8..
    unsigned long long acc[8][4];
#pragma unroll
    for (int ri = 0; ri < 8; ri++)
#pragma unroll
        for (int j = 0; j < 4; j++) acc[ri][j] = 0ull;
    for (int k = 0; k < D; k += 4) {
        ulonglong2 b0a = *(const ulonglong2*)(Ws + (k + 0) * 132 + tx * 8);
        ulonglong2 b0b = *(const ulonglong2*)(Ws + (k + 0) * 132 + tx * 8 + 4);
        ulonglong2 b1a = *(const ulonglong2*)(Ws + (k + 1) * 132 + tx * 8);
        ulonglong2 b1b = *(const ulonglong2*)(Ws + (k + 1) * 132 + tx * 8 + 4);
        ulonglong2 b2a = *(const ulonglong2*)(Ws + (k + 2) * 132 + tx * 8);
        ulonglong2 b2b = *(const ulonglong2*)(Ws + (k + 2) * 132 + tx * 8 + 4);
        ulonglong2 b3a = *(const ulonglong2*)(Ws + (k + 3) * 132 + tx * 8);
        ulonglong2 b3b = *(const ulonglong2*)(Ws + (k + 3) * 132 + tx * 8 + 4);
#pragma unroll
        for (int ri = 0; ri < 8; ri++) {
            float4 a = *(const float4*)(Xs + (ty * 8 + ri) * 132 + k);
            unsigned long long t;
            t = pk2(a.x);
            acc[ri][0] = ffma2(t, b0a.x, acc[ri][0]); acc[ri][1] = ffma2(t, b0a.y, acc[ri][1]);
            acc[ri][2] = ffma2(t, b0b.x, acc[ri][2]); acc[ri][3] = ffma2(t, b0b.y, acc[ri][3]);
            t = pk2(a.y);
            acc[ri][0] = ffma2(t, b1a.x, acc[ri][0]); acc[ri][1] = ffma2(t, b1a.y, acc[ri][1]);
            acc[ri][2] = ffma2(t, b1b.x, acc[ri][2]); acc[ri][3] = ffma2(t, b1b.y, acc[ri][3]);
            t = pk2(a.z);
            acc[ri][0] = ffma2(t, b2a.x, acc[ri][0]); acc[ri][1] = ffma2(t, b2a.y, acc[ri][1]);
            acc[ri][2] = ffma2(t, b2b.x, acc[ri][2]); acc[ri][3] = ffma2(t, b2b.y, acc[ri][3]);
            t = pk2(a.w);
            acc[ri][0] = ffma2(t, b3a.x, acc[ri][0]); acc[ri][1] = ffma2(t, b3a.y, acc[ri][1]);
            acc[ri][2] = ffma2(t, b3b.x, acc[ri][2]); acc[ri][3] = ffma2(t, b3b.y, acc[ri][3]);
        }
    }
#pragma unroll
    for (int ri = 0; ri < 8; ri++) {
        int r = row0 + ty * 8 + ri;
        if (r < rows) {
            float2 p0 = upk2(acc[ri][0]), p1 = upk2(acc[ri][1]);
            float2 p2 = upk2(acc[ri][2]), p3 = upk2(acc[ri][3]);
            *(float4*)(Y + (size_t)r * D + tx * 8)     = make_float4(p0.x, p0.y, p1.x, p1.y);
            *(float4*)(Y + (size_t)r * D + tx * 8 + 4) = make_float4(p2.x, p2.y, p3.x, p3.y);
        }
    }
}

// ---------------- fused edge pass: ex = exp(att.lrelu(xl[src]+xr[dst])); segsum ----------------
__global__ void __launch_bounds__(256) k_edge12(const void* __restrict__ ei,
                                                const float* __restrict__ att) {
    int lane = threadIdx.x & 31;
    int wid = (blockIdx.x * blockDim.x + threadIdx.x) >> 5;
    int nw = (gridDim.x * blockDim.x) >> 5;
    int is64 = d_is64;
    float4 av = ((const float4*)att)[lane];
    for (int e = wid * 2; e < EE; e += nw * 2) {
        int s1 = eidx(ei, is64, e);
        int dd1 = eidx(ei, is64, (long long)EE + e);
        int s2 = eidx(ei, is64, e + 1);
        int dd2 = eidx(ei, is64, (long long)EE + e + 1);
        float4 l1 = ((const float4*)(d_xl + (size_t)s1 * D))[lane];
        float4 r1 = ((const float4*)(d_xr + (size_t)dd1 * D))[lane];
        float4 l2 = ((const float4*)(d_xl + (size_t)s2 * D))[lane];
        float4 r2 = ((const float4*)(d_xr + (size_t)dd2 * D))[lane];
        float zx, zy, zz, zw, p1, p2;
        zx = l1.x + r1.x; zy = l1.y + r1.y; zz = l1.z + r1.z; zw = l1.w + r1.w;
        zx = zx > 0.f ? zx : NEG * zx; zy = zy > 0.f ? zy : NEG * zy;
        zz = zz > 0.f ? zz : NEG * zz; zw = zw > 0.f ? zw : NEG * zw;
        p1 = av.x * zx + av.y * zy + av.z * zz + av.w * zw;
        zx = l2.x + r2.x; zy = l2.y + r2.y; zz = l2.z + r2.z; zw = l2.w + r2.w;
        zx = zx > 0.f ? zx : NEG * zx; zy = zy > 0.f ? zy : NEG * zy;
        zz = zz > 0.f ? zz : NEG * zz; zw = zw > 0.f ? zw : NEG * zw;
        p2 = av.x * zx + av.y * zy + av.z * zz + av.w * zw;
#pragma unroll
        for (int o = 16; o; o >>= 1) {
            p1 += __shfl_xor_sync(~0u, p1, o);
            p2 += __shfl_xor_sync(~0u, p2, o);
        }
        if (lane == 0) {
            float e1 = expf(p1), e2 = expf(p2);
            d_ew[e] = e1;     atomicAdd(&d_ssum[dd1], e1);
            d_ew[e + 1] = e2; atomicAdd(&d_ssum[dd2], e2);
        }
    }
}

// ---------------- edge pass 3a (scalar): c[src] += ew[e]/ssum[dst] ----------------
__global__ void k_edge3a(const void* __restrict__ ei) {
    int i = blockIdx.x * blockDim.x + threadIdx.x;
    if (i >= EE) return;
    int is64 = d_is64;
    int src = eidx(ei, is64, i);
    int dst = eidx(ei, is64, (long long)EE + i);
    float w = d_ew[i] / d_ssum[dst];
    atomicAdd(&d_csrc[src], w);
}

// ---------------- dense pass: g += c[r] * xl[r] ----------------
__global__ void __launch_bounds__(256) k_dense() {
    __shared__ float sg[D];
    int lane = threadIdx.x & 31, w = threadIdx.x >> 5;
    if (threadIdx.x < D) sg[threadIdx.x] = 0.f;
    __syncthreads();
    int gw = blockIdx.x * 8 + w;
    int nw = gridDim.x * 8;
    float4 acc = make_float4(0.f, 0.f, 0.f, 0.f);
    for (int r = gw; r < NSN; r += nw) {
        float cv = d_csrc[r];
        float4 v = ((const float4*)(d_xl + (size_t)r * D))[lane];
        acc.x += cv * v.x; acc.y += cv * v.y; acc.z += cv * v.z; acc.w += cv * v.w;
    }
    atomicAdd(&sg[lane * 4 + 0], acc.x);
    atomicAdd(&sg[lane * 4 + 1], acc.y);
    atomicAdd(&sg[lane * 4 + 2], acc.z);
    atomicAdd(&sg[lane * 4 + 3], acc.w);
    __syncthreads();
    if (threadIdx.x < D) atomicAdd(&d_gacc[threadIdx.x], sg[threadIdx.x]);
}

// ---------------- finalize pooled g -> d_inp ----------------
__global__ void k_fing(const float* __restrict__ conv_bias) {
    int t = threadIdx.x;
    if (t < D) d_inp[t] = d_gacc[t] * (1.0f / (float)NMD) + conv_bias[t];
}

// ---------------- merged sample(step-1) + LSTM(step) + pred layer1 ----------------
__global__ void __launch_bounds__(512) k_step(
    const float* __restrict__ Wih, const float* __restrict__ Whh,
    const float* __restrict__ bih, const float* __restrict__ bhh,
    const float* __restrict__ W1,  const float* __restrict__ b1,
    const float* __restrict__ emb, float* __restrict__ out, int step) {
    __shared__ float si[D], sh[D], sg[4 * D], snh[D];
    __shared__ int sAct;
    int t = threadIdx.x, lane = t & 31;
    const float NI = neginf();
    if (step > 0) {
        if (t < 32) {   // warp 0: reduce GLOG partials for previous step
            float B = NI; int BI = 0; float M = NI, S = 0.f;
            for (int i = lane; i < GLOG; i += 32) {
                float b = d_pm_best[i]; int bidx = d_pm_bi[i];
                if (b > B || (b == B && bidx < BI)) { B = b; BI = bidx; }
                lsmerge(M, S, d_pm_lm[i], d_pm_ls[i]);
            }
#pragma unroll
            for (int o = 16; o; o >>= 1) {
                float ob = __shfl_xor_sync(~0u, B, o);
                int oi = __shfl_xor_sync(~0u, BI, o);
                if (ob > B || (ob == B && oi < BI)) { B = ob; BI = oi; }
                float om = __shfl_xor_sync(~0u, M, o);
                float os = __shfl_xor_sync(~0u, S, o);
                lsmerge(M, S, om, os);
            }
            if (lane == 0) {
                out[step - 1] = (float)BI;
                out[HOR + step - 1] = d_logits[BI] - (M + logf(S));
                sAct = BI;
            }
        }
        __syncthreads();
        if (t < D) si[t] = emb[(size_t)sAct * D + t];
    } else {
        if (t < D) si[t] = d_inp[t];
    }
    if (t < D) sh[t] = d_h[t];
    __syncthreads();
    float acc = bih[t] + bhh[t];
    const float4* wi = (const float4*)(Wih + (size_t)t * D);
    const float4* wh = (const float4*)(Whh + (size_t)t * D);
#pragma unroll 8
    for (int k = 0; k < 32; k++) {
        float4 a = wi[k]; float4 b = wh[k];
        float4 iv = *(const float4*)(si + 4 * k);
        float4 hv = *(const float4*)(sh + 4 * k);
        acc += a.x * iv.x + a.y * iv.y + a.z * iv.z + a.w * iv.w;
        acc += b.x * hv.x + b.y * hv.y + b.z * hv.z + b.w * hv.w;
    }
    sg[t] = acc;
    __syncthreads();
    if (t < D) {
        float ig = 1.f / (1.f + expf(-sg[t]));
        float fg = 1.f / (1.f + expf(-sg[D + t]));
        float gg = tanhf(sg[2 * D + t]);
        float og = 1.f / (1.f + expf(-sg[3 * D + t]));
        float c = fg * d_c[t] + ig * gg;
        float h = og * tanhf(c);
        d_c[t] = c; d_h[t] = h; snh[t] = h;
        if (step == HOR - 1) { out[2 * HOR + t] = h; out[2 * HOR + D + t] = c; }
    }
    __syncthreads();
    if (t < D) {
        float a2 = b1[t];
        const float4* w1 = (const float4*)(W1 + (size_t)t * D);
#pragma unroll 8
        for (int k = 0; k < 32; k++) {
            float4 a = w1[k];
            float4 hv = *(const float4*)(snh + 4 * k);
            a2 += a.x * hv.x + a.y * hv.y + a.z * hv.z + a.w * hv.w;
        }
        d_h2[t] = a2 > 0.f ? a2 : 0.f;
    }
}

// ---------------- logits + gumbel + online softmax partials ----------------
__global__ void __launch_bounds__(256) k_logits(const float* __restrict__ W2,
                                                const float* __restrict__ b2, int step) {
    __shared__ float sh2[D];
    __shared__ float wbest[8]; __shared__ int wbi[8];
    __shared__ float wlm[8], wls[8];
    int t = threadIdx.x, lane = t & 31, w = t >> 5;
    if (t < D) sh2[t] = d_h2[t];
    __syncthreads();
    uint2 key = d_keys[step];
    float4 h0 = *(const float4*)(sh2 + lane * 4);
    int wid = (blockIdx.x * blockDim.x + t) >> 5;
    int nw = (gridDim.x * blockDim.x) >> 5;
    float best = neginf();
    int bi = 0;
    float lm = best, ls = 0.f;
    for (int r = wid; r < NMD; r += nw) {
        float4 wv = *(const float4*)(W2 + (size_t)r * D + lane * 4);
        float p = wv.x * h0.x + wv.y * h0.y + wv.z * h0.z + wv.w * h0.w;
#pragma unroll
        for (int o = 16; o; o >>= 1) p += __shfl_xor_sync(~0u, p, o);
        if (lane == 0) {
            float l = p + b2[r];
            d_logits[r] = l;
            uint2 tr = tf2x32(key.x, key.y, 0u, (unsigned)r);
            unsigned bits = tr.x ^ tr.y;
            float u = __uint_as_float((bits >> 9) | 0x3f800000u) - 1.0f;
            if (u == 0.f) u = 1.17549435e-38f;
            float gum = -logf(-logf(u));
            float sc = gum + l;
            if (sc > best) { best = sc; bi = r; }
            if (l > lm) { ls = ls * expf(lm - l) + 1.f; lm = l; }
            else        { ls += expf(l - lm); }
        }
    }
    if (lane == 0) { wbest[w] = best; wbi[w] = bi; wlm[w] = lm; wls[w] = ls; }
    __syncthreads();
    if (t == 0) {
        float B = neginf(); int BI = 0;
        float M = B, S = 0.f;
        for (int i = 0; i < 8; i++) {
            if (wbest[i] > B || (wbest[i] == B && wbi[i] < BI)) { B = wbest[i]; BI = wbi[i]; }
            lsmerge(M, S, wlm[i], wls[i]);
        }
        d_pm_best[blockIdx.x] = B; d_pm_bi[blockIdx.x] = BI;
        d_pm_lm[blockIdx.x] = M;  d_pm_ls[blockIdx.x] = S;
    }
}

// ---------------- final sample (last step) ----------------
__global__ void k_final(float* __restrict__ out) {
    int lane = threadIdx.x;
    const float NI = neginf();
    float B = NI; int BI = 0; float M = NI, S = 0.f;
    for (int i = lane; i < GLOG; i += 32) {
        float b = d_pm_best[i]; int bidx = d_pm_bi[i];
        if (b > B || (b == B && bidx < BI)) { B = b; BI = bidx; }
        lsmerge(M, S, d_pm_lm[i], d_pm_ls[i]);
    }
#pragma unroll
    for (int o = 16; o; o >>= 1) {
        float ob = __shfl_xor_sync(~0u, B, o);
        int oi = __shfl_xor_sync(~0u, BI, o);
        if (ob > B || (ob == B && oi < BI)) { B = ob; BI = oi; }
        float om = __shfl_xor_sync(~0u, M, o);
        float os = __shfl_xor_sync(~0u, S, o);
        lsmerge(M, S, om, os);
    }
    if (lane == 0) {
        out[HOR - 1] = (float)BI;
        out[2 * HOR - 1] = d_logits[BI] - (M + logf(S));
    }
}

// ---------------- launch ----------------
extern "C" void kernel_launch(void* const* d_in, const int* in_sizes, int n_in,
                              void* d_out, int out_size) {
    const float* state_features = (const float*)d_in[0];
    const float* model_features = (const float*)d_in[1];
    const void*  edge_index     = d_in[2];
    const float* W_l   = (const float*)d_in[3];
    const float* W_r   = (const float*)d_in[4];
    const float* att   = (const float*)d_in[5];
    const float* cbias = (const float*)d_in[6];
    const float* Wih   = (const float*)d_in[7];
    const float* Whh   = (const float*)d_in[8];
    const float* bih   = (const float*)d_in[9];
    const float* bhh   = (const float*)d_in[10];
    const float* W1    = (const float*)d_in[11];
    const float* b1    = (const float*)d_in[12];
    const float* W2    = (const float*)d_in[13];
    const float* b2    = (const float*)d_in[14];
    const float* emb   = (const float*)d_in[15];
    float* out = (float*)d_out;

    const int smem2 = 2 * 128 * 132 * (int)sizeof(float);  // 135168
    cudaFuncSetAttribute(k_gemm2, cudaFuncAttributeMaxDynamicSharedMemorySize, smem2);

    float* xl = nullptr; float* xr = nullptr;
    cudaGetSymbolAddress((void**)&xl, d_xl);
    cudaGetSymbolAddress((void**)&xr, d_xr);

    k_init<<<(NSN + 255) / 256, 256>>>(edge_index);
    k_gemm2<<<(NMD + 127) / 128, 256, smem2>>>(model_features, W_r, xr, NMD);
    k_nop<<<1, 32>>>();
    k_gemm2<<<(NSN + 127) / 128, 256, smem2>>>(state_features, W_l, xl, NSN);  // profiled slot
    k_edge12<<<1184, 256>>>(edge_index, att);
    k_edge3a<<<(EE + 255) / 256, 256>>>(edge_index);
    k_dense<<<296, 256>>>();
    k_fing<<<1, 128>>>(cbias);
    for (int s = 0; s < HOR; s++) {
        k_step<<<1, 512>>>(Wih, Whh, bih, bhh, W1, b1, emb, out, s);
        k_logits<<<GLOG, 256>>>(W2, b2, s);
    }
    k_final<<<1, 32>>>(out);
    (void)in_sizes; (void)n_in; (void)out_size;
}

// round 7
// speedup vs baseline: 1.9006x; 1.3244x over previous
#include <cuda_runtime.h>
#include <cstdint>
#include <cstddef>

#define NSN  100000
#define NMD  50000
#define EE   600000
#define D    128
#define HOR  8
#define NEG  0.2f
#define GLOG 256   // blocks for k_logits

// ---------------- device scratch ----------------
__device__ float    d_xl[(size_t)NSN * D];
__device__ float    d_xr[(size_t)NMD * D];
__device__ float    d_ew[EE];                  // exp(e) per edge
__device__ float    d_ssum[NMD];               // segment sum of exp
__device__ float    d_csrc[NSN];               // per-src scalar weight
__device__ __align__(16) float d_gacc[D];
__device__ __align__(16) float d_inp[D];
__device__ __align__(16) float d_h[D];
__device__ __align__(16) float d_c[D];
__device__ __align__(16) float d_h2[D];
__device__ float    d_logits[NMD];
__device__ float    d_pm_best[GLOG];
__device__ int      d_pm_bi[GLOG];
__device__ float    d_pm_lm[GLOG];
__device__ float    d_pm_ls[GLOG];
__device__ uint2    d_keys[HOR];
__device__ int      d_is64;

// ---------------- helpers ----------------
__device__ __forceinline__ int eidx(const void* ei, int is64, long long pos) {
    return is64 ? (int)((const long long*)ei)[pos] : ((const int*)ei)[pos];
}
__device__ __forceinline__ float neginf() { return __int_as_float((int)0xff800000); }

// packed f32x2 FMA (PTX-only FFMA2: 2 fp32 FMA per fma-pipe slot)
__device__ __forceinline__ unsigned long long pk2(float x) {
    unsigned long long r; asm("mov.b64 %0, {%1, %1};" : "=l"(r) : "f"(x)); return r;
}
__device__ __forceinline__ unsigned long long ffma2(unsigned long long a,
                                                   unsigned long long b,
                                                   unsigned long long c) {
    unsigned long long d_;
    asm("fma.rn.f32x2 %0, %1, %2, %3;" : "=l"(d_) : "l"(a), "l"(b), "l"(c));
    return d_;
}
__device__ __forceinline__ float2 upk2(unsigned long long v) {
    float lo, hi; asm("mov.b64 {%0, %1}, %2;" : "=f"(lo), "=f"(hi) : "l"(v));
    return make_float2(lo, hi);
}

// JAX threefry2x32, 20 rounds
__device__ __forceinline__ uint2 tf2x32(unsigned k0, unsigned k1, unsigned x0, unsigned x1) {
    unsigned k2 = k0 ^ k1 ^ 0x1BD11BDAu;
    x0 += k0; x1 += k1;
#define TFR(r) { x0 += x1; x1 = (x1 << (r)) | (x1 >> (32 - (r))); x1 ^= x0; }
    TFR(13) TFR(15) TFR(26) TFR(6)   x0 += k1; x1 += k2 + 1u;
    TFR(17) TFR(29) TFR(16) TFR(24)  x0 += k2; x1 += k0 + 2u;
    TFR(13) TFR(15) TFR(26) TFR(6)   x0 += k0; x1 += k1 + 3u;
    TFR(17) TFR(29) TFR(16) TFR(24)  x0 += k1; x1 += k2 + 4u;
    TFR(13) TFR(15) TFR(26) TFR(6)   x0 += k2; x1 += k0 + 5u;
#undef TFR
    return make_uint2(x0, x1);
}

// merge two (max, sum) online-softmax states
__device__ __forceinline__ void lsmerge(float& M, float& S, float m, float s) {
    if (s > 0.f) {
        if (m > M) { S = S * expf(M - m) + s; M = m; }
        else       { S += s * expf(m - M); }
    }
}

// ---------------- init ----------------
__global__ void k_init(const void* ei) {
    int i = blockIdx.x * blockDim.x + threadIdx.x;
    if (i < NMD) d_ssum[i] = 0.f;
    if (i < NSN) d_csrc[i] = 0.f;
    if (i < D)   { d_gacc[i] = 0.f; d_h[i] = 0.f; d_c[i] = 0.f; }
    if (i == 0) {
        const int* p = (const int*)ei;
        int all0 = 1;
        for (int j = 1; j < 201; j += 2) all0 &= (p[j] == 0);
        d_is64 = all0;
        for (int j = 0; j < HOR; j++) {
            uint2 r = tf2x32(0u, 42u, 0u, (unsigned)j);
            d_keys[j] = make_uint2(r.x, r.y);
        }
    }
}

__global__ void k_nop() {}

// ---------------- GEMM3: W^T in smem only, X direct from gmem, 2 CTAs/SM ----------------
__global__ void __launch_bounds__(256, 2) k_gemm3(const float* __restrict__ X,
                                                  const float* __restrict__ W,
                                                  float* __restrict__ Y, int rows) {
    extern __shared__ float Ws[];   // [128][132] : Ws[k][col] = W[col][k]
    for (int i = threadIdx.x; i < D * D; i += 256) {
        int col = i >> 7, k = i & 127;
        Ws[k * 132 + col] = W[i];
    }
    __syncthreads();
    int tx = threadIdx.x & 15, ty = threadIdx.x >> 4;  // cols tx*8.., rows ty*8..
    int row0 = blockIdx.x << 7;
    const float* xr_[8];
#pragma unroll
    for (int ri = 0; ri < 8; ri++) {
        int r = row0 + ty * 8 + ri;
        xr_[ri] = X + (size_t)(r < rows ? r : 0) * D;
    }
    unsigned long long acc[8][4];
#pragma unroll
    for (int ri = 0; ri < 8; ri++)
#pragma unroll
        for (int j = 0; j < 4; j++) acc[ri][j] = 0ull;
#pragma unroll 2
    for (int k = 0; k < D; k += 4) {
        ulonglong2 b0a = *(const ulonglong2*)(Ws + (k + 0) * 132 + tx * 8);
        ulonglong2 b0b = *(const ulonglong2*)(Ws + (k + 0) * 132 + tx * 8 + 4);
        ulonglong2 b1a = *(const ulonglong2*)(Ws + (k + 1) * 132 + tx * 8);
        ulonglong2 b1b = *(const ulonglong2*)(Ws + (k + 1) * 132 + tx * 8 + 4);
        ulonglong2 b2a = *(const ulonglong2*)(Ws + (k + 2) * 132 + tx * 8);
        ulonglong2 b2b = *(const ulonglong2*)(Ws + (k + 2) * 132 + tx * 8 + 4);
        ulonglong2 b3a = *(const ulonglong2*)(Ws + (k + 3) * 132 + tx * 8);
        ulonglong2 b3b = *(const ulonglong2*)(Ws + (k + 3) * 132 + tx * 8 + 4);
#pragma unroll
        for (int ri = 0; ri < 8; ri++) {
            float4 a = *(const float4*)(xr_[ri] + k);
            unsigned long long t;
            t = pk2(a.x);
            acc[ri][0] = ffma2(t, b0a.x, acc[ri][0]); acc[ri][1] = ffma2(t, b0a.y, acc[ri][1]);
            acc[ri][2] = ffma2(t, b0b.x, acc[ri][2]); acc[ri][3] = ffma2(t, b0b.y, acc[ri][3]);
            t = pk2(a.y);
            acc[ri][0] = ffma2(t, b1a.x, acc[ri][0]); acc[ri][1] = ffma2(t, b1a.y, acc[ri][1]);
            acc[ri][2] = ffma2(t, b1b.x, acc[ri][2]); acc[ri][3] = ffma2(t, b1b.y, acc[ri][3]);
            t = pk2(a.z);
            acc[ri][0] = ffma2(t, b2a.x, acc[ri][0]); acc[ri][1] = ffma2(t, b2a.y, acc[ri][1]);
            acc[ri][2] = ffma2(t, b2b.x, acc[ri][2]); acc[ri][3] = ffma2(t, b2b.y, acc[ri][3]);
            t = pk2(a.w);
            acc[ri][0] = ffma2(t, b3a.x, acc[ri][0]); acc[ri][1] = ffma2(t, b3a.y, acc[ri][1]);
            acc[ri][2] = ffma2(t, b3b.x, acc[ri][2]); acc[ri][3] = ffma2(t, b3b.y, acc[ri][3]);
        }
    }
#pragma unroll
    for (int ri = 0; ri < 8; ri++) {
        int r = row0 + ty * 8 + ri;
        if (r < rows) {
            float2 p0 = upk2(acc[ri][0]), p1 = upk2(acc[ri][1]);
            float2 p2 = upk2(acc[ri][2]), p3 = upk2(acc[ri][3]);
            *(float4*)(Y + (size_t)r * D + tx * 8)     = make_float4(p0.x, p0.y, p1.x, p1.y);
            *(float4*)(Y + (size_t)r * D + tx * 8 + 4) = make_float4(p2.x, p2.y, p3.x, p3.y);
        }
    }
}

// ---------------- fused edge pass: ex = exp(att.lrelu(xl[src]+xr[dst])); segsum ----------------
__global__ void __launch_bounds__(256) k_edge12(const void* __restrict__ ei,
                                                const float* __restrict__ att) {
    int lane = threadIdx.x & 31;
    int wid = (blockIdx.x * blockDim.x + threadIdx.x) >> 5;
    int nw = (gridDim.x * blockDim.x) >> 5;
    int is64 = d_is64;
    float4 av = ((const float4*)att)[lane];
    for (int e = wid * 2; e < EE; e += nw * 2) {
        int s1 = eidx(ei, is64, e);
        int dd1 = eidx(ei, is64, (long long)EE + e);
        int s2 = eidx(ei, is64, e + 1);
        int dd2 = eidx(ei, is64, (long long)EE + e + 1);
        float4 l1 = ((const float4*)(d_xl + (size_t)s1 * D))[lane];
        float4 r1 = ((const float4*)(d_xr + (size_t)dd1 * D))[lane];
        float4 l2 = ((const float4*)(d_xl + (size_t)s2 * D))[lane];
        float4 r2 = ((const float4*)(d_xr + (size_t)dd2 * D))[lane];
        float zx, zy, zz, zw, p1, p2;
        zx = l1.x + r1.x; zy = l1.y + r1.y; zz = l1.z + r1.z; zw = l1.w + r1.w;
        zx = zx > 0.f ? zx : NEG * zx; zy = zy > 0.f ? zy : NEG * zy;
        zz = zz > 0.f ? zz : NEG * zz; zw = zw > 0.f ? zw : NEG * zw;
        p1 = av.x * zx + av.y * zy + av.z * zz + av.w * zw;
        zx = l2.x + r2.x; zy = l2.y + r2.y; zz = l2.z + r2.z; zw = l2.w + r2.w;
        zx = zx > 0.f ? zx : NEG * zx; zy = zy > 0.f ? zy : NEG * zy;
        zz = zz > 0.f ? zz : NEG * zz; zw = zw > 0.f ? zw : NEG * zw;
        p2 = av.x * zx + av.y * zy + av.z * zz + av.w * zw;
#pragma unroll
        for (int o = 16; o; o >>= 1) {
            p1 += __shfl_xor_sync(~0u, p1, o);
            p2 += __shfl_xor_sync(~0u, p2, o);
        }
        if (lane == 0) {
            float e1 = expf(p1), e2 = expf(p2);
            d_ew[e] = e1;     atomicAdd(&d_ssum[dd1], e1);
            d_ew[e + 1] = e2; atomicAdd(&d_ssum[dd2], e2);
        }
    }
}

// ---------------- edge pass 3a (scalar): c[src] += ew[e]/ssum[dst] ----------------
__global__ void k_edge3a(const void* __restrict__ ei) {
    int i = blockIdx.x * blockDim.x + threadIdx.x;
    if (i >= EE) return;
    int is64 = d_is64;
    int src = eidx(ei, is64, i);
    int dst = eidx(ei, is64, (long long)EE + i);
    float w = d_ew[i] / d_ssum[dst];
    atomicAdd(&d_csrc[src], w);
}

// ---------------- dense pass: g += c[r] * xl[r] ----------------
__global__ void __launch_bounds__(256) k_dense() {
    __shared__ float sg[D];
    int lane = threadIdx.x & 31, w = threadIdx.x >> 5;
    if (threadIdx.x < D) sg[threadIdx.x] = 0.f;
    __syncthreads();
    int gw = blockIdx.x * 8 + w;
    int nw = gridDim.x * 8;
    float4 acc = make_float4(0.f, 0.f, 0.f, 0.f);
    for (int r = gw; r < NSN; r += nw) {
        float cv = d_csrc[r];
        float4 v = ((const float4*)(d_xl + (size_t)r * D))[lane];
        acc.x += cv * v.x; acc.y += cv * v.y; acc.z += cv * v.z; acc.w += cv * v.w;
    }
    atomicAdd(&sg[lane * 4 + 0], acc.x);
    atomicAdd(&sg[lane * 4 + 1], acc.y);
    atomicAdd(&sg[lane * 4 + 2], acc.z);
    atomicAdd(&sg[lane * 4 + 3], acc.w);
    __syncthreads();
    if (threadIdx.x < D) atomicAdd(&d_gacc[threadIdx.x], sg[threadIdx.x]);
}

// ---------------- finalize pooled g -> d_inp ----------------
__global__ void k_fing(const float* __restrict__ conv_bias) {
    int t = threadIdx.x;
    if (t < D) d_inp[t] = d_gacc[t] * (1.0f / (float)NMD) + conv_bias[t];
}

// ---------------- merged sample(step-1) + LSTM(step) + pred layer1 ----------------
__global__ void __launch_bounds__(512) k_step(
    const float* __restrict__ Wih, const float* __restrict__ Whh,
    const float* __restrict__ bih, const float* __restrict__ bhh,
    const float* __restrict__ W1,  const float* __restrict__ b1,
    const float* __restrict__ emb, float* __restrict__ out, int step) {
    __shared__ float si[D], sh[D], sg[4 * D], snh[D];
    __shared__ int sAct;
    int t = threadIdx.x, lane = t & 31;
    const float NI = neginf();
    if (step > 0) {
        if (t < 32) {   // warp 0: reduce GLOG partials for previous step
            float B = NI; int BI = 0; float M = NI, S = 0.f;
            for (int i = lane; i < GLOG; i += 32) {
                float b = d_pm_best[i]; int bidx = d_pm_bi[i];
                if (b > B || (b == B && bidx < BI)) { B = b; BI = bidx; }
                lsmerge(M, S, d_pm_lm[i], d_pm_ls[i]);
            }
#pragma unroll
            for (int o = 16; o; o >>= 1) {
                float ob = __shfl_xor_sync(~0u, B, o);
                int oi = __shfl_xor_sync(~0u, BI, o);
                if (ob > B || (ob == B && oi < BI)) { B = ob; BI = oi; }
                float om = __shfl_xor_sync(~0u, M, o);
                float os = __shfl_xor_sync(~0u, S, o);
                lsmerge(M, S, om, os);
            }
            if (lane == 0) {
                out[step - 1] = (float)BI;
                out[HOR + step - 1] = d_logits[BI] - (M + logf(S));
                sAct = BI;
            }
        }
        __syncthreads();
        if (t < D) si[t] = emb[(size_t)sAct * D + t];
    } else {
        if (t < D) si[t] = d_inp[t];
    }
    if (t < D) sh[t] = d_h[t];
    __syncthreads();
    float acc = bih[t] + bhh[t];
    const float4* wi = (const float4*)(Wih + (size_t)t * D);
    const float4* wh = (const float4*)(Whh + (size_t)t * D);
#pragma unroll 8
    for (int k = 0; k < 32; k++) {
        float4 a = wi[k]; float4 b = wh[k];
        float4 iv = *(const float4*)(si + 4 * k);
        float4 hv = *(const float4*)(sh + 4 * k);
        acc += a.x * iv.x + a.y * iv.y + a.z * iv.z + a.w * iv.w;
        acc += b.x * hv.x + b.y * hv.y + b.z * hv.z + b.w * hv.w;
    }
    sg[t] = acc;
    __syncthreads();
    if (t < D) {
        float ig = 1.f / (1.f + expf(-sg[t]));
        float fg = 1.f / (1.f + expf(-sg[D + t]));
        float gg = tanhf(sg[2 * D + t]);
        float og = 1.f / (1.f + expf(-sg[3 * D + t]));
        float c = fg * d_c[t] + ig * gg;
        float h = og * tanhf(c);
        d_c[t] = c; d_h[t] = h; snh[t] = h;
        if (step == HOR - 1) { out[2 * HOR + t] = h; out[2 * HOR + D + t] = c; }
    }
    __syncthreads();
    if (t < D) {
        float a2 = b1[t];
        const float4* w1 = (const float4*)(W1 + (size_t)t * D);
#pragma unroll 8
        for (int k = 0; k < 32; k++) {
            float4 a = w1[k];
            float4 hv = *(const float4*)(snh + 4 * k);
            a2 += a.x * hv.x + a.y * hv.y + a.z * hv.z + a.w * hv.w;
        }
        d_h2[t] = a2 > 0.f ? a2 : 0.f;
    }
}

// ---------------- logits + gumbel + online softmax (lane-parallel RNG) ----------------
__global__ void __launch_bounds__(256) k_logits(const float* __restrict__ W2,
                                                const float* __restrict__ b2, int step) {
    __shared__ float sh2[D];
    __shared__ float wbest[8]; __shared__ int wbi[8];
    __shared__ float wlm[8], wls[8];
    int t = threadIdx.x, lane = t & 31, w = t >> 5;
    if (t < D) sh2[t] = d_h2[t];
    __syncthreads();
    uint2 key = d_keys[step];
    float4 h0 = ((const float4*)sh2)[lane];
    int gw = (blockIdx.x * blockDim.x + t) >> 5;
    int nw = (gridDim.x * blockDim.x) >> 5;
    const float NI = neginf();
    float best = NI; int bi = 0x7fffffff;
    float lm = NI, ls = 0.f;
    for (int base = gw * 32; base < NMD; base += nw * 32) {
        int myrow = base + lane;
        float myl = 0.f;
        int jmax = NMD - base; if (jmax > 32) jmax = 32;
        for (int j = 0; j < jmax; j++) {
            float4 wv = ((const float4*)(W2 + (size_t)(base + j) * D))[lane];
            float p = wv.x * h0.x + wv.y * h0.y + wv.z * h0.z + wv.w * h0.w;
#pragma unroll
            for (int o = 16; o; o >>= 1) p += __shfl_xor_sync(~0u, p, o);
            if (lane == j) myl = p;
        }
        if (myrow < NMD) {
            myl += b2[myrow];
            d_logits[myrow] = myl;
            uint2 tr = tf2x32(key.x, key.y, 0u, (unsigned)myrow);
            unsigned bits = tr.x ^ tr.y;
            float u = __uint_as_float((bits >> 9) | 0x3f800000u) - 1.0f;
            if (u == 0.f) u = 1.17549435e-38f;
            float score = myl - logf(-logf(u));
            if (score > best || (score == best && myrow < bi)) { best = score; bi = myrow; }
            lsmerge(lm, ls, myl, 1.f);
        }
    }
    // warp reduce the four states
#pragma unroll
    for (int o = 16; o; o >>= 1) {
        float ob = __shfl_xor_sync(~0u, best, o);
        int oi = __shfl_xor_sync(~0u, bi, o);
        if (ob > best || (ob == best && oi < bi)) { best = ob; bi = oi; }
        float om = __shfl_xor_sync(~0u, lm, o);
        float os = __shfl_xor_sync(~0u, ls, o);
        lsmerge(lm, ls, om, os);
    }
    if (lane == 0) { wbest[w] = best; wbi[w] = bi; wlm[w] = lm; wls[w] = ls; }
    __syncthreads();
    if (t == 0) {
        float B = NI; int BI = 0x7fffffff;
        float M = NI, S = 0.f;
        for (int i = 0; i < 8; i++) {
            if (wbest[i] > B || (wbest[i] == B && wbi[i] < BI)) { B = wbest[i]; BI = wbi[i]; }
            lsmerge(M, S, wlm[i], wls[i]);
        }
        d_pm_best[blockIdx.x] = B; d_pm_bi[blockIdx.x] = BI;
        d_pm_lm[blockIdx.x] = M;  d_pm_ls[blockIdx.x] = S;
    }
}

// ---------------- final sample (last step) ----------------
__global__ void k_final(float* __restrict__ out) {
    int lane = threadIdx.x;
    const float NI = neginf();
    float B = NI; int BI = 0; float M = NI, S = 0.f;
    for (int i = lane; i < GLOG; i += 32) {
        float b = d_pm_best[i]; int bidx = d_pm_bi[i];
        if (b > B || (b == B && bidx < BI)) { B = b; BI = bidx; }
        lsmerge(M, S, d_pm_lm[i], d_pm_ls[i]);
    }
#pragma unroll
    for (int o = 16; o; o >>= 1) {
        float ob = __shfl_xor_sync(~0u, B, o);
        int oi = __shfl_xor_sync(~0u, BI, o);
        if (ob > B || (ob == B && oi < BI)) { B = ob; BI = oi; }
        float om = __shfl_xor_sync(~0u, M, o);
        float os = __shfl_xor_sync(~0u, S, o);
        lsmerge(M, S, om, os);
    }
    if (lane == 0) {
        out[HOR - 1] = (float)BI;
        out[2 * HOR - 1] = d_logits[BI] - (M + logf(S));
    }
}

// ---------------- launch ----------------
extern "C" void kernel_launch(void* const* d_in, const int* in_sizes, int n_in,
                              void* d_out, int out_size) {
    const float* state_features = (const float*)d_in[0];
    const float* model_features = (const float*)d_in[1];
    const void*  edge_index     = d_in[2];
    const float* W_l   = (const float*)d_in[3];
    const float* W_r   = (const float*)d_in[4];
    const float* att   = (const float*)d_in[5];
    const float* cbias = (const float*)d_in[6];
    const float* Wih   = (const float*)d_in[7];
    const float* Whh   = (const float*)d_in[8];
    const float* bih   = (const float*)d_in[9];
    const float* bhh   = (const float*)d_in[10];
    const float* W1    = (const float*)d_in[11];
    const float* b1    = (const float*)d_in[12];
    const float* W2    = (const float*)d_in[13];
    const float* b2    = (const float*)d_in[14];
    const float* emb   = (const float*)d_in[15];
    float* out = (float*)d_out;

    const int smem3 = 128 * 132 * (int)sizeof(float);  // 67584
    cudaFuncSetAttribute(k_gemm3, cudaFuncAttributeMaxDynamicSharedMemorySize, smem3);

    float* xl = nullptr; float* xr = nullptr;
    cudaGetSymbolAddress((void**)&xl, d_xl);
    cudaGetSymbolAddress((void**)&xr, d_xr);

    k_init<<<(NSN + 255) / 256, 256>>>(edge_index);
    k_gemm3<<<(NMD + 127) / 128, 256, smem3>>>(model_features, W_r, xr, NMD);
    k_nop<<<1, 32>>>();
    k_gemm3<<<(NSN + 127) / 128, 256, smem3>>>(state_features, W_l, xl, NSN);  // profiled slot
    k_edge12<<<1184, 256>>>(edge_index, att);
    k_edge3a<<<(EE + 255) / 256, 256>>>(edge_index);
    k_dense<<<296, 256>>>();
    k_fing<<<1, 128>>>(cbias);
    for (int s = 0; s < HOR; s++) {
        k_step<<<1, 512>>>(Wih, Whh, bih, bhh, W1, b1, emb, out, s);
        k_logits<<<GLOG, 256>>>(W2, b2, s);
    }
    k_final<<<1, 32>>>(out);
    (void)in_sizes; (void)n_in; (void)out_size;
}

// round 9
// speedup vs baseline: 2.2780x; 1.1985x over previous
#include <cuda_runtime.h>
#include <cuda_bf16.h>
#include <cstdint>
#include <cstddef>

#define NSN  100000
#define NMD  50000
#define EE   600000
#define D    128
#define HOR  8
#define NEG  0.2f
#define GLOG 128   // blocks for k_roll

// ---------------- device scratch ----------------
__device__ float    d_xl[(size_t)NSN * D];
__device__ float    d_xr[(size_t)NMD * D];
__device__ float    d_ew[EE];
__device__ float    d_ssum[NMD];
__device__ float    d_csrc[NSN];
__device__ __align__(16) float d_gacc[D];
__device__ __align__(16) float d_inp[D];
__device__ __align__(16) float d_hbuf[2][D];
__device__ __align__(16) float d_cbuf[2][D];
__device__ float    d_pm_best[2][GLOG];
__device__ int      d_pm_bi[2][GLOG];
__device__ float    d_pm_bl[2][GLOG];
__device__ float    d_pm_lm[2][GLOG];
__device__ float    d_pm_ls[2][GLOG];
__device__ uint2    d_keys[HOR];
__device__ int      d_is64;
// packed bf16 hi/lo weights, k-pairwise (u32 = bf16[k even] | bf16[k odd]<<16),
// laid out [kp][n] with row stride 136 (pre-padded for conflict-free LDS)
#define WSTRIDE 136
__device__ __align__(16) uint32_t d_wphl[64 * WSTRIDE];
__device__ __align__(16) uint32_t d_wpll[64 * WSTRIDE];
__device__ __align__(16) uint32_t d_wphr[64 * WSTRIDE];
__device__ __align__(16) uint32_t d_wplr[64 * WSTRIDE];

// ---------------- helpers ----------------
__device__ __forceinline__ int eidx(const void* ei, int is64, long long pos) {
    return is64 ? (int)((const long long*)ei)[pos] : ((const int*)ei)[pos];
}
__device__ __forceinline__ float neginf() { return __int_as_float((int)0xff800000); }

__device__ __forceinline__ uint2 tf2x32(unsigned k0, unsigned k1, unsigned x0, unsigned x1) {
    unsigned k2 = k0 ^ k1 ^ 0x1BD11BDAu;
    x0 += k0; x1 += k1;
#define TFR(r) { x0 += x1; x1 = (x1 << (r)) | (x1 >> (32 - (r))); x1 ^= x0; }
    TFR(13) TFR(15) TFR(26) TFR(6)   x0 += k1; x1 += k2 + 1u;
    TFR(17) TFR(29) TFR(16) TFR(24)  x0 += k2; x1 += k0 + 2u;
    TFR(13) TFR(15) TFR(26) TFR(6)   x0 += k0; x1 += k1 + 3u;
    TFR(17) TFR(29) TFR(16) TFR(24)  x0 += k1; x1 += k2 + 4u;
    TFR(13) TFR(15) TFR(26) TFR(6)   x0 += k2; x1 += k0 + 5u;
#undef TFR
    return make_uint2(x0, x1);
}

__device__ __forceinline__ void lsmerge(float& M, float& S, float m, float s) {
    if (s > 0.f) {
        if (m > M) { S = S * expf(M - m) + s; M = m; }
        else       { S += s * expf(m - M); }
    }
}

__device__ __forceinline__ void mma_bf16(float* c, const uint32_t* a, uint32_t b0, uint32_t b1) {
    asm volatile(
        "mma.sync.aligned.m16n8k16.row.col.f32.bf16.bf16.f32 "
        "{%0,%1,%2,%3}, {%4,%5,%6,%7}, {%8,%9}, {%0,%1,%2,%3};"
        : "+f"(c[0]), "+f"(c[1]), "+f"(c[2]), "+f"(c[3])
        : "r"(a[0]), "r"(a[1]), "r"(a[2]), "r"(a[3]), "r"(b0), "r"(b1));
}

__device__ __forceinline__ uint32_t pack_hi(float e, float o) {
    unsigned a = __bfloat16_as_ushort(__float2bfloat16_rn(e));
    unsigned b = __bfloat16_as_ushort(__float2bfloat16_rn(o));
    return a | (b << 16);
}
__device__ __forceinline__ uint32_t pack_lo(float e, float o) {
    float he = __bfloat162float(__float2bfloat16_rn(e));
    float ho = __bfloat162float(__float2bfloat16_rn(o));
    unsigned a = __bfloat16_as_ushort(__float2bfloat16_rn(e - he));
    unsigned b = __bfloat16_as_ushort(__float2bfloat16_rn(o - ho));
    return a | (b << 16);
}

// ---------------- init ----------------
__global__ void k_init(const void* ei) {
    int i = blockIdx.x * blockDim.x + threadIdx.x;
    if (i < NMD) d_ssum[i] = 0.f;
    if (i < NSN) d_csrc[i] = 0.f;
    if (i < D) {
        d_gacc[i] = 0.f;
        d_hbuf[0][i] = 0.f; d_cbuf[0][i] = 0.f;
        d_hbuf[1][i] = 0.f; d_cbuf[1][i] = 0.f;
    }
    if (i == 0) {
        const int* p = (const int*)ei;
        int all0 = 1;
        for (int j = 1; j < 201; j += 2) all0 &= (p[j] == 0);
        d_is64 = all0;
        for (int j = 0; j < HOR; j++) {
            uint2 r = tf2x32(0u, 42u, 0u, (unsigned)j);
            d_keys[j] = make_uint2(r.x, r.y);
        }
    }
}

// ---------------- W [n][k] -> packed bf16 hi/lo [kp][n] (stride 136) ----------------
__global__ void k_wconv(const float* __restrict__ Wl, const float* __restrict__ Wr) {
    int idx = blockIdx.x * blockDim.x + threadIdx.x;
    if (idx >= 64 * 128) return;
    int kp = idx >> 7, n = idx & 127;
    int o = kp * WSTRIDE + n;
    float le = Wl[n * D + 2 * kp], lo = Wl[n * D + 2 * kp + 1];
    d_wphl[o] = pack_hi(le, lo);
    d_wpll[o] = pack_lo(le, lo);
    float re = Wr[n * D + 2 * kp], ro = Wr[n * D + 2 * kp + 1];
    d_wphr[o] = pack_hi(re, ro);
    d_wplr[o] = pack_lo(re, ro);
}

// ---------------- HMMA GEMM: Y[r][c] = sum_k X[r][k]*W[c][k], bf16 split ----------------
#define SM_GB (64 * WSTRIDE)   // u32 per B copy
__global__ void __launch_bounds__(256, 2) k_gemm_mma(const float* __restrict__ X,
                                                     const uint32_t* __restrict__ gbh,
                                                     const uint32_t* __restrict__ gbl,
                                                     float* __restrict__ Y, int rows) {
    extern __shared__ uint32_t bs[];
    uint32_t* Bh = bs;
    uint32_t* Bl = bs + SM_GB;
    for (int i = threadIdx.x; i < SM_GB / 4; i += 256) {
        ((uint4*)Bh)[i] = ((const uint4*)gbh)[i];
        ((uint4*)Bl)[i] = ((const uint4*)gbl)[i];
    }
    __syncthreads();
    int w = threadIdx.x >> 5, lane = threadIdx.x & 31;
    int q = lane & 3, g = lane >> 2;
    int r0 = blockIdx.x * 128 + w * 16 + g;   // rows r0 and r0+8
    const float* x0 = X + (size_t)(r0 < rows ? r0 : rows - 1) * D;
    const float* x1 = X + (size_t)(r0 + 8 < rows ? r0 + 8 : rows - 1) * D;
    float acc[16][4];
#pragma unroll
    for (int nt = 0; nt < 16; nt++) { acc[nt][0] = acc[nt][1] = acc[nt][2] = acc[nt][3] = 0.f; }

    for (int k8 = 0; k8 < 8; k8++) {
        int c0 = k8 * 16 + 2 * q;
        float2 p0 = *(const float2*)(x0 + c0);
        float2 p1 = *(const float2*)(x1 + c0);
        float2 p2 = *(const float2*)(x0 + c0 + 8);
        float2 p3 = *(const float2*)(x1 + c0 + 8);
        uint32_t ah[4], al[4];
        ah[0] = pack_hi(p0.x, p0.y); al[0] = pack_lo(p0.x, p0.y);
        ah[1] = pack_hi(p1.x, p1.y); al[1] = pack_lo(p1.x, p1.y);
        ah[2] = pack_hi(p2.x, p2.y); al[2] = pack_lo(p2.x, p2.y);
        ah[3] = pack_hi(p3.x, p3.y); al[3] = pack_lo(p3.x, p3.y);
        int kb0 = (k8 * 8 + q) * WSTRIDE + g;
        int kb1 = (k8 * 8 + q + 4) * WSTRIDE + g;
#pragma unroll
        for (int nt = 0; nt < 16; nt++) {
            uint32_t bh0 = Bh[kb0 + nt * 8];
            uint32_t bh1 = Bh[kb1 + nt * 8];
            uint32_t bl0 = Bl[kb0 + nt * 8];
            uint32_t bl1 = Bl[kb1 + nt * 8];
            mma_bf16(acc[nt], ah, bh0, bh1);
            mma_bf16(acc[nt], ah, bl0, bl1);
            mma_bf16(acc[nt], al, bh0, bh1);
        }
    }
    // epilogue: c0,c1 -> row r0 cols 2q,2q+1; c2,c3 -> row r0+8
    bool w0 = r0 < rows, w1 = (r0 + 8) < rows;
#pragma unroll
    for (int nt = 0; nt < 16; nt++) {
        int col = nt * 8 + 2 * q;
        if (w0) *(float2*)(Y + (size_t)r0 * D + col) = make_float2(acc[nt][0], acc[nt][1]);
        if (w1) *(float2*)(Y + (size_t)(r0 + 8) * D + col) = make_float2(acc[nt][2], acc[nt][3]);
    }
}

// ---------------- fused edge pass ----------------
__global__ void __launch_bounds__(256) k_edge12(const void* __restrict__ ei,
                                                const float* __restrict__ att) {
    int lane = threadIdx.x & 31;
    int wid = (blockIdx.x * blockDim.x + threadIdx.x) >> 5;
    int nw = (gridDim.x * blockDim.x) >> 5;
    int is64 = d_is64;
    float4 av = ((const float4*)att)[lane];
    for (int e = wid * 2; e < EE; e += nw * 2) {
        int s1 = eidx(ei, is64, e);
        int dd1 = eidx(ei, is64, (long long)EE + e);
        int s2 = eidx(ei, is64, e + 1);
        int dd2 = eidx(ei, is64, (long long)EE + e + 1);
        float4 l1 = ((const float4*)(d_xl + (size_t)s1 * D))[lane];
        float4 r1 = ((const float4*)(d_xr + (size_t)dd1 * D))[lane];
        float4 l2 = ((const float4*)(d_xl + (size_t)s2 * D))[lane];
        float4 r2 = ((const float4*)(d_xr + (size_t)dd2 * D))[lane];
        float zx, zy, zz, zw, p1, p2;
        zx = l1.x + r1.x; zy = l1.y + r1.y; zz = l1.z + r1.z; zw = l1.w + r1.w;
        zx = zx > 0.f ? zx : NEG * zx; zy = zy > 0.f ? zy : NEG * zy;
        zz = zz > 0.f ? zz : NEG * zz; zw = zw > 0.f ? zw : NEG * zw;
        p1 = av.x * zx + av.y * zy + av.z * zz + av.w * zw;
        zx = l2.x + r2.x; zy = l2.y + r2.y; zz = l2.z + r2.z; zw = l2.w + r2.w;
        zx = zx > 0.f ? zx : NEG * zx; zy = zy > 0.f ? zy : NEG * zy;
        zz = zz > 0.f ? zz : NEG * zz; zw = zw > 0.f ? zw : NEG * zw;
        p2 = av.x * zx + av.y * zy + av.z * zz + av.w * zw;
#pragma unroll
        for (int o = 16; o; o >>= 1) {
            p1 += __shfl_xor_sync(~0u, p1, o);
            p2 += __shfl_xor_sync(~0u, p2, o);
        }
        if (lane == 0) {
            float e1 = expf(p1), e2 = expf(p2);
            d_ew[e] = e1;     atomicAdd(&d_ssum[dd1], e1);
            d_ew[e + 1] = e2; atomicAdd(&d_ssum[dd2], e2);
        }
    }
}

__global__ void k_edge3a(const void* __restrict__ ei) {
    int i = blockIdx.x * blockDim.x + threadIdx.x;
    if (i >= EE) return;
    int is64 = d_is64;
    int src = eidx(ei, is64, i);
    int dst = eidx(ei, is64, (long long)EE + i);
    atomicAdd(&d_csrc[src], d_ew[i] / d_ssum[dst]);
}

__global__ void __launch_bounds__(256) k_dense() {
    __shared__ float sg[D];
    int lane = threadIdx.x & 31, w = threadIdx.x >> 5;
    if (threadIdx.x < D) sg[threadIdx.x] = 0.f;
    __syncthreads();
    int gw = blockIdx.x * 8 + w;
    int nw = gridDim.x * 8;
    float4 acc = make_float4(0.f, 0.f, 0.f, 0.f);
    for (int r = gw; r < NSN; r += nw) {
        float cv = d_csrc[r];
        float4 v = ((const float4*)(d_xl + (size_t)r * D))[lane];
        acc.x += cv * v.x; acc.y += cv * v.y; acc.z += cv * v.z; acc.w += cv * v.w;
    }
    atomicAdd(&sg[lane * 4 + 0], acc.x);
    atomicAdd(&sg[lane * 4 + 1], acc.y);
    atomicAdd(&sg[lane * 4 + 2], acc.z);
    atomicAdd(&sg[lane * 4 + 3], acc.w);
    __syncthreads();
    if (threadIdx.x < D) atomicAdd(&d_gacc[threadIdx.x], sg[threadIdx.x]);
}

__global__ void k_fing(const float* __restrict__ conv_bias) {
    int t = threadIdx.x;
    if (t < D) d_inp[t] = d_gacc[t] * (1.0f / (float)NMD) + conv_bias[t];
}

// ---------------- fused rollout step ----------------
__global__ void __launch_bounds__(256) k_roll(
    const float* __restrict__ Wih, const float* __restrict__ Whh,
    const float* __restrict__ bih, const float* __restrict__ bhh,
    const float* __restrict__ W1,  const float* __restrict__ b1,
    const float* __restrict__ W2,  const float* __restrict__ b2,
    const float* __restrict__ emb, float* __restrict__ out, int step) {
    __shared__ float si[D], sh[D], sg[4 * D], snh[D], sh2[D];
    __shared__ float wbest[8], wbl[8], wlm[8], wls[8];
    __shared__ int wbi[8], sAct;
    int t = threadIdx.x, lane = t & 31, w = t >> 5;
    const float NI = neginf();
    int rp = step & 1, wp = step & 1;
    int pmr = (step - 1) & 1;

    if (step > 0) {
        if (t < 32) {
            float B = NI, BL = 0.f; int BI = 0x7fffffff; float M = NI, S = 0.f;
            for (int i = lane; i < GLOG; i += 32) {
                float b = d_pm_best[pmr][i]; int bidx = d_pm_bi[pmr][i];
                if (b > B || (b == B && bidx < BI)) { B = b; BI = bidx; BL = d_pm_bl[pmr][i]; }
                lsmerge(M, S, d_pm_lm[pmr][i], d_pm_ls[pmr][i]);
            }
#pragma unroll
            for (int o = 16; o; o >>= 1) {
                float ob = __shfl_xor_sync(~0u, B, o);
                int oi = __shfl_xor_sync(~0u, BI, o);
                float ol = __shfl_xor_sync(~0u, BL, o);
                if (ob > B || (ob == B && oi < BI)) { B = ob; BI = oi; BL = ol; }
                float om = __shfl_xor_sync(~0u, M, o);
                float os = __shfl_xor_sync(~0u, S, o);
                lsmerge(M, S, om, os);
            }
            if (lane == 0) {
                if (blockIdx.x == 0) {
                    out[step - 1] = (float)BI;
                    out[HOR + step - 1] = BL - (M + logf(S));
                }
                sAct = BI;
            }
        }
        __syncthreads();
        if (t < D) si[t] = emb[(size_t)sAct * D + t];
    } else {
        if (t < D) si[t] = d_inp[t];
    }
    if (t < D) sh[t] = d_hbuf[rp][t];
    __syncthreads();

#pragma unroll
    for (int half = 0; half < 2; half++) {
        int row = t + half * 256;
        float acc = bih[row] + bhh[row];
        const float4* wi = (const float4*)(Wih + (size_t)row * D);
        const float4* wh = (const float4*)(Whh + (size_t)row * D);
#pragma unroll 8
        for (int k = 0; k < 32; k++) {
            float4 a = wi[k]; float4 b = wh[k];
            float4 iv = *(const float4*)(si + 4 * k);
            float4 hv = *(const float4*)(sh + 4 * k);
            acc += a.x * iv.x + a.y * iv.y + a.z * iv.z + a.w * iv.w;
            acc += b.x * hv.x + b.y * hv.y + b.z * hv.z + b.w * hv.w;
        }
        sg[row] = acc;
    }
    __syncthreads();
    if (t < D) {
        float ig = 1.f / (1.f + expf(-sg[t]));
        float fg = 1.f / (1.f + expf(-sg[D + t]));
        float gg = tanhf(sg[2 * D + t]);
        float og = 1.f / (1.f + expf(-sg[3 * D + t]));
        float c = fg * d_cbuf[rp][t] + ig * gg;
        float h = og * tanhf(c);
        snh[t] = h;
        if (blockIdx.x == 0) {
            d_cbuf[1 - rp][t] = c; d_hbuf[1 - rp][t] = h;
            if (step == HOR - 1) { out[2 * HOR + t] = h; out[2 * HOR + D + t] = c; }
        }
    }
    __syncthreads();
    if (t < D) {
        float a2 = b1[t];
        const float4* w1 = (const float4*)(W1 + (size_t)t * D);
#pragma unroll 8
        for (int k = 0; k < 32; k++) {
            float4 a = w1[k];
            float4 hv = *(const float4*)(snh + 4 * k);
            a2 += a.x * hv.x + a.y * hv.y + a.z * hv.z + a.w * hv.w;
        }
        sh2[t] = a2 > 0.f ? a2 : 0.f;
    }
    __syncthreads();

    uint2 key = d_keys[step];
    float4 h0 = ((const float4*)sh2)[lane];
    int gw = (blockIdx.x * blockDim.x + t) >> 5;
    int nw = (GLOG * 256) >> 5;
    float best = NI, bl = 0.f; int bi = 0x7fffffff;
    float lm = NI, ls = 0.f;
    for (int base = gw * 32; base < NMD; base += nw * 32) {
        int myrow = base + lane;
        float myl = 0.f;
        int jmax = NMD - base; if (jmax > 32) jmax = 32;
        for (int j = 0; j < jmax; j++) {
            float4 wv = ((const float4*)(W2 + (size_t)(base + j) * D))[lane];
            float p = wv.x * h0.x + wv.y * h0.y + wv.z * h0.z + wv.w * h0.w;
#pragma unroll
            for (int o = 16; o; o >>= 1) p += __shfl_xor_sync(~0u, p, o);
            if (lane == j) myl = p;
        }
        if (myrow < NMD) {
            myl += b2[myrow];
            uint2 tr = tf2x32(key.x, key.y, 0u, (unsigned)myrow);
            unsigned bits = tr.x ^ tr.y;
            float u = __uint_as_float((bits >> 9) | 0x3f800000u) - 1.0f;
            if (u == 0.f) u = 1.17549435e-38f;
            float score = myl - logf(-logf(u));
            if (score > best || (score == best && myrow < bi)) { best = score; bi = myrow; bl = myl; }
            lsmerge(lm, ls, myl, 1.f);
        }
    }
#pragma unroll
    for (int o = 16; o; o >>= 1) {
        float ob = __shfl_xor_sync(~0u, best, o);
        int oi = __shfl_xor_sync(~0u, bi, o);
        float ol = __shfl_xor_sync(~0u, bl, o);
        if (ob > best || (ob == best && oi < bi)) { best = ob; bi = oi; bl = ol; }
        float om = __shfl_xor_sync(~0u, lm, o);
        float os = __shfl_xor_sync(~0u, ls, o);
        lsmerge(lm, ls, om, os);
    }
    if (lane == 0) { wbest[w] = best; wbi[w] = bi; wbl[w] = bl; wlm[w] = lm; wls[w] = ls; }
    __syncthreads();
    if (t == 0) {
        float B = NI, BL = 0.f; int BI = 0x7fffffff; float M = NI, S = 0.f;
        for (int i = 0; i < 8; i++) {
            if (wbest[i] > B || (wbest[i] == B && wbi[i] < BI)) { B = wbest[i]; BI = wbi[i]; BL = wbl[i]; }
            lsmerge(M, S, wlm[i], wls[i]);
        }
        d_pm_best[wp][blockIdx.x] = B; d_pm_bi[wp][blockIdx.x] = BI; d_pm_bl[wp][blockIdx.x] = BL;
        d_pm_lm[wp][blockIdx.x] = M;  d_pm_ls[wp][blockIdx.x] = S;
    }
}

// ---------------- final sample ----------------
__global__ void k_final(float* __restrict__ out) {
    int lane = threadIdx.x;
    const float NI = neginf();
    int pb = (HOR - 1) & 1;
    float B = NI, BL = 0.f; int BI = 0; float M = NI, S = 0.f;
    for (int i = lane; i < GLOG; i += 32) {
        float b = d_pm_best[pb][i]; int bidx = d_pm_bi[pb][i];
        if (b > B || (b == B && bidx < BI)) { B = b; BI = bidx; BL = d_pm_bl[pb][i]; }
        lsmerge(M, S, d_pm_lm[pb][i], d_pm_ls[pb][i]);
    }
#pragma unroll
    for (int o = 16; o; o >>= 1) {
        float ob = __shfl_xor_sync(~0u, B, o);
        int oi = __shfl_xor_sync(~0u, BI, o);
        float ol = __shfl_xor_sync(~0u, BL, o);
        if (ob > B || (ob == B && oi < BI)) { B = ob; BI = oi; BL = ol; }
        float om = __shfl_xor_sync(~0u, M, o);
        float os = __shfl_xor_sync(~0u, S, o);
        lsmerge(M, S, om, os);
    }
    if (lane == 0) {
        out[HOR - 1] = (float)BI;
        out[2 * HOR - 1] = BL - (M + logf(S));
    }
}

// ---------------- launch ----------------
extern "C" void kernel_launch(void* const* d_in, const int* in_sizes, int n_in,
                              void* d_out, int out_size) {
    const float* state_features = (const float*)d_in[0];
    const float* model_features = (const float*)d_in[1];
    const void*  edge_index     = d_in[2];
    const float* W_l   = (const float*)d_in[3];
    const float* W_r   = (const float*)d_in[4];
    const float* att   = (const float*)d_in[5];
    const float* cbias = (const float*)d_in[6];
    const float* Wih   = (const float*)d_in[7];
    const float* Whh   = (const float*)d_in[8];
    const float* bih   = (const float*)d_in[9];
    const float* bhh   = (const float*)d_in[10];
    const float* W1    = (const float*)d_in[11];
    const float* b1    = (const float*)d_in[12];
    const float* W2    = (const float*)d_in[13];
    const float* b2    = (const float*)d_in[14];
    const float* emb   = (const float*)d_in[15];
    float* out = (float*)d_out;

    const int smemB = 2 * SM_GB * (int)sizeof(uint32_t);  // 69632
    cudaFuncSetAttribute(k_gemm_mma, cudaFuncAttributeMaxDynamicSharedMemorySize, smemB);

    float* xl; float* xr;
    cudaGetSymbolAddress((void**)&xl, d_xl);
    cudaGetSymbolAddress((void**)&xr, d_xr);
    uint32_t *whl, *wll, *whr, *wlr;
    cudaGetSymbolAddress((void**)&whl, d_wphl);
    cudaGetSymbolAddress((void**)&wll, d_wpll);
    cudaGetSymbolAddress((void**)&whr, d_wphr);
    cudaGetSymbolAddress((void**)&wlr, d_wplr);

    k_init<<<(NSN + 255) / 256, 256>>>(edge_index);
    k_wconv<<<32, 256>>>(W_l, W_r);
    k_gemm_mma<<<(NMD + 127) / 128, 256, smemB>>>(model_features, whr, wlr, xr, NMD);
    k_gemm_mma<<<(NSN + 127) / 128, 256, smemB>>>(state_features, whl, wll, xl, NSN);  // profiled
    k_edge12<<<1184, 256>>>(edge_index, att);
    k_edge3a<<<(EE + 255) / 256, 256>>>(edge_index);
    k_dense<<<296, 256>>>();
    k_fing<<<1, 128>>>(cbias);
    for (int s = 0; s < HOR; s++)
        k_roll<<<GLOG, 256>>>(Wih, Whh, bih, bhh, W1, b1, W2, b2, emb, out, s);
    k_final<<<1, 32>>>(out);
    (void)in_sizes; (void)n_in; (void)out_size;
}

// round 10
// speedup vs baseline: 2.4850x; 1.0909x over previous
#include <cuda_runtime.h>
#include <cuda_bf16.h>
#include <cstdint>
#include <cstddef>

#define NSN  100000
#define NMD  50000
#define EE   600000
#define D    128
#define HOR  8
#define NEG  0.2f
#define GLOG 128   // blocks for k_roll

// ---------------- device scratch ----------------
__device__ float    d_xl[(size_t)NSN * D];
__device__ float    d_xr[(size_t)NMD * D];
__device__ float    d_ew[EE];
__device__ float    d_ssum[NMD];
__device__ float    d_csrc[NSN];
__device__ __align__(16) float d_gacc[D];
__device__ __align__(16) float d_inp[D];
__device__ __align__(16) float d_hbuf[2][D];
__device__ __align__(16) float d_cbuf[2][D];
__device__ float    d_pm_best[2][GLOG];
__device__ int      d_pm_bi[2][GLOG];
__device__ float    d_pm_bl[2][GLOG];
__device__ float    d_pm_lm[2][GLOG];
__device__ float    d_pm_ls[2][GLOG];
__device__ uint2    d_keys[HOR];
__device__ int      d_is64;
#define WSTRIDE 136
__device__ __align__(16) uint32_t d_wphl[64 * WSTRIDE];
__device__ __align__(16) uint32_t d_wpll[64 * WSTRIDE];
__device__ __align__(16) uint32_t d_wphr[64 * WSTRIDE];
__device__ __align__(16) uint32_t d_wplr[64 * WSTRIDE];

// ---------------- helpers ----------------
__device__ __forceinline__ int eidx(const void* ei, int is64, long long pos) {
    return is64 ? (int)((const long long*)ei)[pos] : ((const int*)ei)[pos];
}
__device__ __forceinline__ float neginf() { return __int_as_float((int)0xff800000); }

__device__ __forceinline__ uint2 tf2x32(unsigned k0, unsigned k1, unsigned x0, unsigned x1) {
    unsigned k2 = k0 ^ k1 ^ 0x1BD11BDAu;
    x0 += k0; x1 += k1;
#define TFR(r) { x0 += x1; x1 = (x1 << (r)) | (x1 >> (32 - (r))); x1 ^= x0; }
    TFR(13) TFR(15) TFR(26) TFR(6)   x0 += k1; x1 += k2 + 1u;
    TFR(17) TFR(29) TFR(16) TFR(24)  x0 += k2; x1 += k0 + 2u;
    TFR(13) TFR(15) TFR(26) TFR(6)   x0 += k0; x1 += k1 + 3u;
    TFR(17) TFR(29) TFR(16) TFR(24)  x0 += k1; x1 += k2 + 4u;
    TFR(13) TFR(15) TFR(26) TFR(6)   x0 += k2; x1 += k0 + 5u;
#undef TFR
    return make_uint2(x0, x1);
}

__device__ __forceinline__ void lsmerge(float& M, float& S, float m, float s) {
    if (s > 0.f) {
        if (m > M) { S = S * expf(M - m) + s; M = m; }
        else       { S += s * expf(m - M); }
    }
}

__device__ __forceinline__ void mma_bf16(float* c, const uint32_t* a, uint32_t b0, uint32_t b1) {
    asm volatile(
        "mma.sync.aligned.m16n8k16.row.col.f32.bf16.bf16.f32 "
        "{%0,%1,%2,%3}, {%4,%5,%6,%7}, {%8,%9}, {%0,%1,%2,%3};"
        : "+f"(c[0]), "+f"(c[1]), "+f"(c[2]), "+f"(c[3])
        : "r"(a[0]), "r"(a[1]), "r"(a[2]), "r"(a[3]), "r"(b0), "r"(b1));
}

__device__ __forceinline__ uint32_t pack_hi(float e, float o) {
    unsigned a = __bfloat16_as_ushort(__float2bfloat16_rn(e));
    unsigned b = __bfloat16_as_ushort(__float2bfloat16_rn(o));
    return a | (b << 16);
}
__device__ __forceinline__ uint32_t pack_lo(float e, float o) {
    float he = __bfloat162float(__float2bfloat16_rn(e));
    float ho = __bfloat162float(__float2bfloat16_rn(o));
    unsigned a = __bfloat16_as_ushort(__float2bfloat16_rn(e - he));
    unsigned b = __bfloat16_as_ushort(__float2bfloat16_rn(o - ho));
    return a | (b << 16);
}

// ---------------- init ----------------
__global__ void k_init(const void* ei) {
    int i = blockIdx.x * blockDim.x + threadIdx.x;
    if (i < NMD) d_ssum[i] = 0.f;
    if (i < NSN) d_csrc[i] = 0.f;
    if (i < D) {
        d_gacc[i] = 0.f;
        d_hbuf[0][i] = 0.f; d_cbuf[0][i] = 0.f;
        d_hbuf[1][i] = 0.f; d_cbuf[1][i] = 0.f;
    }
    if (i == 0) {
        const int* p = (const int*)ei;
        int all0 = 1;
        for (int j = 1; j < 201; j += 2) all0 &= (p[j] == 0);
        d_is64 = all0;
        for (int j = 0; j < HOR; j++) {
            uint2 r = tf2x32(0u, 42u, 0u, (unsigned)j);
            d_keys[j] = make_uint2(r.x, r.y);
        }
    }
}

// ---------------- W [n][k] -> packed bf16 hi/lo [kp][n] (stride 136) ----------------
__global__ void k_wconv(const float* __restrict__ Wl, const float* __restrict__ Wr) {
    int idx = blockIdx.x * blockDim.x + threadIdx.x;
    if (idx >= 64 * 128) return;
    int kp = idx >> 7, n = idx & 127;
    int o = kp * WSTRIDE + n;
    float le = Wl[n * D + 2 * kp], lo = Wl[n * D + 2 * kp + 1];
    d_wphl[o] = pack_hi(le, lo);
    d_wpll[o] = pack_lo(le, lo);
    float re = Wr[n * D + 2 * kp], ro = Wr[n * D + 2 * kp + 1];
    d_wphr[o] = pack_hi(re, ro);
    d_wplr[o] = pack_lo(re, ro);
}

// ---------------- HMMA GEMM: Y[r][c] = sum_k X[r][k]*W[c][k], bf16 split ----------------
#define SM_GB (64 * WSTRIDE)
__global__ void __launch_bounds__(256, 2) k_gemm_mma(const float* __restrict__ X,
                                                     const uint32_t* __restrict__ gbh,
                                                     const uint32_t* __restrict__ gbl,
                                                     float* __restrict__ Y, int rows) {
    extern __shared__ uint32_t bs[];
    uint32_t* Bh = bs;
    uint32_t* Bl = bs + SM_GB;
    for (int i = threadIdx.x; i < SM_GB / 4; i += 256) {
        ((uint4*)Bh)[i] = ((const uint4*)gbh)[i];
        ((uint4*)Bl)[i] = ((const uint4*)gbl)[i];
    }
    __syncthreads();
    int w = threadIdx.x >> 5, lane = threadIdx.x & 31;
    int q = lane & 3, g = lane >> 2;
    int r0 = blockIdx.x * 128 + w * 16 + g;
    const float* x0 = X + (size_t)(r0 < rows ? r0 : rows - 1) * D;
    const float* x1 = X + (size_t)(r0 + 8 < rows ? r0 + 8 : rows - 1) * D;
    float acc[16][4];
#pragma unroll
    for (int nt = 0; nt < 16; nt++) { acc[nt][0] = acc[nt][1] = acc[nt][2] = acc[nt][3] = 0.f; }

#pragma unroll
    for (int k8 = 0; k8 < 8; k8++) {
        int c0 = k8 * 16 + 2 * q;
        float2 p0 = *(const float2*)(x0 + c0);
        float2 p1 = *(const float2*)(x1 + c0);
        float2 p2 = *(const float2*)(x0 + c0 + 8);
        float2 p3 = *(const float2*)(x1 + c0 + 8);
        uint32_t ah[4], al[4];
        ah[0] = pack_hi(p0.x, p0.y); al[0] = pack_lo(p0.x, p0.y);
        ah[1] = pack_hi(p1.x, p1.y); al[1] = pack_lo(p1.x, p1.y);
        ah[2] = pack_hi(p2.x, p2.y); al[2] = pack_lo(p2.x, p2.y);
        ah[3] = pack_hi(p3.x, p3.y); al[3] = pack_lo(p3.x, p3.y);
        int kb0 = (k8 * 8 + q) * WSTRIDE + g;
        int kb1 = (k8 * 8 + q + 4) * WSTRIDE + g;
#pragma unroll
        for (int nt = 0; nt < 16; nt++) {
            uint32_t bh0 = Bh[kb0 + nt * 8];
            uint32_t bh1 = Bh[kb1 + nt * 8];
            uint32_t bl0 = Bl[kb0 + nt * 8];
            uint32_t bl1 = Bl[kb1 + nt * 8];
            mma_bf16(acc[nt], ah, bh0, bh1);
            mma_bf16(acc[nt], ah, bl0, bl1);
            mma_bf16(acc[nt], al, bh0, bh1);
        }
    }
    bool w0 = r0 < rows, w1 = (r0 + 8) < rows;
#pragma unroll
    for (int nt = 0; nt < 16; nt++) {
        int col = nt * 8 + 2 * q;
        if (w0) *(float2*)(Y + (size_t)r0 * D + col) = make_float2(acc[nt][0], acc[nt][1]);
        if (w1) *(float2*)(Y + (size_t)(r0 + 8) * D + col) = make_float2(acc[nt][2], acc[nt][3]);
    }
}

// ---------------- fused edge pass ----------------
__global__ void __launch_bounds__(256) k_edge12(const void* __restrict__ ei,
                                                const float* __restrict__ att) {
    int lane = threadIdx.x & 31;
    int wid = (blockIdx.x * blockDim.x + threadIdx.x) >> 5;
    int nw = (gridDim.x * blockDim.x) >> 5;
    int is64 = d_is64;
    float4 av = ((const float4*)att)[lane];
    for (int e = wid * 2; e < EE; e += nw * 2) {
        int s1 = eidx(ei, is64, e);
        int dd1 = eidx(ei, is64, (long long)EE + e);
        int s2 = eidx(ei, is64, e + 1);
        int dd2 = eidx(ei, is64, (long long)EE + e + 1);
        float4 l1 = ((const float4*)(d_xl + (size_t)s1 * D))[lane];
        float4 r1 = ((const float4*)(d_xr + (size_t)dd1 * D))[lane];
        float4 l2 = ((const float4*)(d_xl + (size_t)s2 * D))[lane];
        float4 r2 = ((const float4*)(d_xr + (size_t)dd2 * D))[lane];
        float zx, zy, zz, zw, p1, p2;
        zx = l1.x + r1.x; zy = l1.y + r1.y; zz = l1.z + r1.z; zw = l1.w + r1.w;
        zx = zx > 0.f ? zx : NEG * zx; zy = zy > 0.f ? zy : NEG * zy;
        zz = zz > 0.f ? zz : NEG * zz; zw = zw > 0.f ? zw : NEG * zw;
        p1 = av.x * zx + av.y * zy + av.z * zz + av.w * zw;
        zx = l2.x + r2.x; zy = l2.y + r2.y; zz = l2.z + r2.z; zw = l2.w + r2.w;
        zx = zx > 0.f ? zx : NEG * zx; zy = zy > 0.f ? zy : NEG * zy;
        zz = zz > 0.f ? zz : NEG * zz; zw = zw > 0.f ? zw : NEG * zw;
        p2 = av.x * zx + av.y * zy + av.z * zz + av.w * zw;
#pragma unroll
        for (int o = 16; o; o >>= 1) {
            p1 += __shfl_xor_sync(~0u, p1, o);
            p2 += __shfl_xor_sync(~0u, p2, o);
        }
        if (lane == 0) {
            float e1 = expf(p1), e2 = expf(p2);
            d_ew[e] = e1;     atomicAdd(&d_ssum[dd1], e1);
            d_ew[e + 1] = e2; atomicAdd(&d_ssum[dd2], e2);
        }
    }
}

__global__ void k_edge3a(const void* __restrict__ ei) {
    int i = blockIdx.x * blockDim.x + threadIdx.x;
    if (i >= EE) return;
    int is64 = d_is64;
    int src = eidx(ei, is64, i);
    int dst = eidx(ei, is64, (long long)EE + i);
    atomicAdd(&d_csrc[src], d_ew[i] / d_ssum[dst]);
}

__global__ void __launch_bounds__(256) k_dense() {
    __shared__ float sg[D];
    int lane = threadIdx.x & 31, w = threadIdx.x >> 5;
    if (threadIdx.x < D) sg[threadIdx.x] = 0.f;
    __syncthreads();
    int gw = blockIdx.x * 8 + w;
    int nw = gridDim.x * 8;
    float4 acc = make_float4(0.f, 0.f, 0.f, 0.f);
    for (int r = gw; r < NSN; r += nw) {
        float cv = d_csrc[r];
        float4 v = ((const float4*)(d_xl + (size_t)r * D))[lane];
        acc.x += cv * v.x; acc.y += cv * v.y; acc.z += cv * v.z; acc.w += cv * v.w;
    }
    atomicAdd(&sg[lane * 4 + 0], acc.x);
    atomicAdd(&sg[lane * 4 + 1], acc.y);
    atomicAdd(&sg[lane * 4 + 2], acc.z);
    atomicAdd(&sg[lane * 4 + 3], acc.w);
    __syncthreads();
    if (threadIdx.x < D) atomicAdd(&d_gacc[threadIdx.x], sg[threadIdx.x]);
}

__global__ void k_fing(const float* __restrict__ conv_bias) {
    int t = threadIdx.x;
    if (t < D) d_inp[t] = d_gacc[t] * (1.0f / (float)NMD) + conv_bias[t];
}

// ---------------- fused rollout step ----------------
__global__ void __launch_bounds__(256) k_roll(
    const float* __restrict__ Wih, const float* __restrict__ Whh,
    const float* __restrict__ bih, const float* __restrict__ bhh,
    const float* __restrict__ W1,  const float* __restrict__ b1,
    const float* __restrict__ W2,  const float* __restrict__ b2,
    const float* __restrict__ emb, float* __restrict__ out, int step) {
    __shared__ float si[D], sh[D], sg[4 * D], snh[D], sh2[D];
    __shared__ float wbest[8], wbl[8], wlm[8], wls[8];
    __shared__ int wbi[8], sAct;
    int t = threadIdx.x, lane = t & 31, w = t >> 5;
    const float NI = neginf();
    int rp = step & 1, wp = step & 1;
    int pmr = (step - 1) & 1;

    // phase A: sample prev action (redundant per block)
    if (step > 0) {
        if (t < 32) {
            float B = NI, BL = 0.f; int BI = 0x7fffffff; float M = NI, S = 0.f;
            for (int i = lane; i < GLOG; i += 32) {
                float b = d_pm_best[pmr][i]; int bidx = d_pm_bi[pmr][i];
                if (b > B || (b == B && bidx < BI)) { B = b; BI = bidx; BL = d_pm_bl[pmr][i]; }
                lsmerge(M, S, d_pm_lm[pmr][i], d_pm_ls[pmr][i]);
            }
#pragma unroll
            for (int o = 16; o; o >>= 1) {
                float ob = __shfl_xor_sync(~0u, B, o);
                int oi = __shfl_xor_sync(~0u, BI, o);
                float ol = __shfl_xor_sync(~0u, BL, o);
                if (ob > B || (ob == B && oi < BI)) { B = ob; BI = oi; BL = ol; }
                float om = __shfl_xor_sync(~0u, M, o);
                float os = __shfl_xor_sync(~0u, S, o);
                lsmerge(M, S, om, os);
            }
            if (lane == 0) {
                if (blockIdx.x == 0) {
                    out[step - 1] = (float)BI;
                    out[HOR + step - 1] = BL - (M + logf(S));
                }
                sAct = BI;
            }
        }
        __syncthreads();
        if (t < D) si[t] = emb[(size_t)sAct * D + t];
    } else {
        if (t < D) si[t] = d_inp[t];
    }
    if (t < D) sh[t] = d_hbuf[rp][t];
    __syncthreads();

    // LSTM gates (2 independent accumulators to halve dep chain)
#pragma unroll
    for (int half = 0; half < 2; half++) {
        int row = t + half * 256;
        float a0 = bih[row], a1 = bhh[row];
        const float4* wi = (const float4*)(Wih + (size_t)row * D);
        const float4* wh = (const float4*)(Whh + (size_t)row * D);
#pragma unroll 8
        for (int k = 0; k < 32; k++) {
            float4 a = wi[k]; float4 b = wh[k];
            float4 iv = *(const float4*)(si + 4 * k);
            float4 hv = *(const float4*)(sh + 4 * k);
            a0 += a.x * iv.x + a.y * iv.y + a.z * iv.z + a.w * iv.w;
            a1 += b.x * hv.x + b.y * hv.y + b.z * hv.z + b.w * hv.w;
        }
        sg[row] = a0 + a1;
    }
    __syncthreads();
    if (t < D) {
        float ig = 1.f / (1.f + expf(-sg[t]));
        float fg = 1.f / (1.f + expf(-sg[D + t]));
        float gg = tanhf(sg[2 * D + t]);
        float og = 1.f / (1.f + expf(-sg[3 * D + t]));
        float c = fg * d_cbuf[rp][t] + ig * gg;
        float h = og * tanhf(c);
        snh[t] = h;
        if (blockIdx.x == 0) {
            d_cbuf[1 - rp][t] = c; d_hbuf[1 - rp][t] = h;
            if (step == HOR - 1) { out[2 * HOR + t] = h; out[2 * HOR + D + t] = c; }
        }
    }
    __syncthreads();
    if (t < D) {
        float a0 = b1[t], a1 = 0.f;
        const float4* w1 = (const float4*)(W1 + (size_t)t * D);
#pragma unroll 8
        for (int k = 0; k < 32; k += 2) {
            float4 a = w1[k];     float4 hv = *(const float4*)(snh + 4 * k);
            float4 b = w1[k + 1]; float4 h2 = *(const float4*)(snh + 4 * k + 4);
            a0 += a.x * hv.x + a.y * hv.y + a.z * hv.z + a.w * hv.w;
            a1 += b.x * h2.x + b.y * h2.y + b.z * h2.z + b.w * h2.w;
        }
        float a2 = a0 + a1;
        sh2[t] = a2 > 0.f ? a2 : 0.f;
    }
    __syncthreads();

    // phase B: logits + gumbel + online softmax (quad-parallel dots)
    uint2 key = d_keys[step];
    int q = lane & 3, g = lane >> 2;
    float4 hreg[8];
#pragma unroll
    for (int i = 0; i < 8; i++) hreg[i] = ((const float4*)sh2)[i * 4 + q];
    int gw = (blockIdx.x * blockDim.x + t) >> 5;
    int nw = (GLOG * 256) >> 5;
    float best = NI, bl = 0.f; int bi = 0x7fffffff;
    float lm = NI, ls = 0.f;
    for (int base = gw * 32; base < NMD; base += nw * 32) {
        float myl = 0.f;
#pragma unroll
        for (int it = 0; it < 4; it++) {
            int row = base + it * 8 + g;
            float p = 0.f;
            if (row < NMD) {
                const float4* wr = (const float4*)(W2 + (size_t)row * D);
#pragma unroll
                for (int i = 0; i < 8; i++) {
                    float4 wv = wr[i * 4 + q];
                    float4 hv = hreg[i];
                    p += wv.x * hv.x + wv.y * hv.y + wv.z * hv.z + wv.w * hv.w;
                }
            }
            p += __shfl_xor_sync(~0u, p, 1);
            p += __shfl_xor_sync(~0u, p, 2);
            if (q == it) myl = p;
        }
        int myrow = base + q * 8 + g;
        if (myrow < NMD) {
            myl += b2[myrow];
            uint2 tr = tf2x32(key.x, key.y, 0u, (unsigned)myrow);
            unsigned bits = tr.x ^ tr.y;
            float u = __uint_as_float((bits >> 9) | 0x3f800000u) - 1.0f;
            if (u == 0.f) u = 1.17549435e-38f;
            float score = myl - logf(-logf(u));
            if (score > best || (score == best && myrow < bi)) { best = score; bi = myrow; bl = myl; }
            lsmerge(lm, ls, myl, 1.f);
        }
    }
#pragma unroll
    for (int o = 16; o; o >>= 1) {
        float ob = __shfl_xor_sync(~0u, best, o);
        int oi = __shfl_xor_sync(~0u, bi, o);
        float ol = __shfl_xor_sync(~0u, bl, o);
        if (ob > best || (ob == best && oi < bi)) { best = ob; bi = oi; bl = ol; }
        float om = __shfl_xor_sync(~0u, lm, o);
        float os = __shfl_xor_sync(~0u, ls, o);
        lsmerge(lm, ls, om, os);
    }
    if (lane == 0) { wbest[w] = best; wbi[w] = bi; wbl[w] = bl; wlm[w] = lm; wls[w] = ls; }
    __syncthreads();
    if (t == 0) {
        float B = NI, BL = 0.f; int BI = 0x7fffffff; float M = NI, S = 0.f;
        for (int i = 0; i < 8; i++) {
            if (wbest[i] > B || (wbest[i] == B && wbi[i] < BI)) { B = wbest[i]; BI = wbi[i]; BL = wbl[i]; }
            lsmerge(M, S, wlm[i], wls[i]);
        }
        d_pm_best[wp][blockIdx.x] = B; d_pm_bi[wp][blockIdx.x] = BI; d_pm_bl[wp][blockIdx.x] = BL;
        d_pm_lm[wp][blockIdx.x] = M;  d_pm_ls[wp][blockIdx.x] = S;
    }
}

// ---------------- final sample ----------------
__global__ void k_final(float* __restrict__ out) {
    int lane = threadIdx.x;
    const float NI = neginf();
    int pb = (HOR - 1) & 1;
    float B = NI, BL = 0.f; int BI = 0; float M = NI, S = 0.f;
    for (int i = lane; i < GLOG; i += 32) {
        float b = d_pm_best[pb][i]; int bidx = d_pm_bi[pb][i];
        if (b > B || (b == B && bidx < BI)) { B = b; BI = bidx; BL = d_pm_bl[pb][i]; }
        lsmerge(M, S, d_pm_lm[pb][i], d_pm_ls[pb][i]);
    }
#pragma unroll
    for (int o = 16; o; o >>= 1) {
        float ob = __shfl_xor_sync(~0u, B, o);
        int oi = __shfl_xor_sync(~0u, BI, o);
        float ol = __shfl_xor_sync(~0u, BL, o);
        if (ob > B || (ob == B && oi < BI)) { B = ob; BI = oi; BL = ol; }
        float om = __shfl_xor_sync(~0u, M, o);
        float os = __shfl_xor_sync(~0u, S, o);
        lsmerge(M, S, om, os);
    }
    if (lane == 0) {
        out[HOR - 1] = (float)BI;
        out[2 * HOR - 1] = BL - (M + logf(S));
    }
}

// ---------------- launch ----------------
extern "C" void kernel_launch(void* const* d_in, const int* in_sizes, int n_in,
                              void* d_out, int out_size) {
    const float* state_features = (const float*)d_in[0];
    const float* model_features = (const float*)d_in[1];
    const void*  edge_index     = d_in[2];
    const float* W_l   = (const float*)d_in[3];
    const float* W_r   = (const float*)d_in[4];
    const float* att   = (const float*)d_in[5];
    const float* cbias = (const float*)d_in[6];
    const float* Wih   = (const float*)d_in[7];
    const float* Whh   = (const float*)d_in[8];
    const float* bih   = (const float*)d_in[9];
    const float* bhh   = (const float*)d_in[10];
    const float* W1    = (const float*)d_in[11];
    const float* b1    = (const float*)d_in[12];
    const float* W2    = (const float*)d_in[13];
    const float* b2    = (const float*)d_in[14];
    const float* emb   = (const float*)d_in[15];
    float* out = (float*)d_out;

    const int smemB = 2 * SM_GB * (int)sizeof(uint32_t);  // 69632
    cudaFuncSetAttribute(k_gemm_mma, cudaFuncAttributeMaxDynamicSharedMemorySize, smemB);

    float* xl; float* xr;
    cudaGetSymbolAddress((void**)&xl, d_xl);
    cudaGetSymbolAddress((void**)&xr, d_xr);
    uint32_t *whl, *wll, *whr, *wlr;
    cudaGetSymbolAddress((void**)&whl, d_wphl);
    cudaGetSymbolAddress((void**)&wll, d_wpll);
    cudaGetSymbolAddress((void**)&whr, d_wphr);
    cudaGetSymbolAddress((void**)&wlr, d_wplr);

    k_init<<<(NSN + 255) / 256, 256>>>(edge_index);
    k_wconv<<<32, 256>>>(W_l, W_r);
    k_gemm_mma<<<(NMD + 127) / 128, 256, smemB>>>(model_features, whr, wlr, xr, NMD);
    k_gemm_mma<<<(NSN + 127) / 128, 256, smemB>>>(state_features, whl, wll, xl, NSN);  // profiled
    k_edge12<<<1184, 256>>>(edge_index, att);
    k_edge3a<<<(EE + 255) / 256, 256>>>(edge_index);
    k_dense<<<296, 256>>>();
    k_fing<<<1, 128>>>(cbias);
    for (int s = 0; s < HOR; s++)
        k_roll<<<GLOG, 256>>>(Wih, Whh, bih, bhh, W1, b1, W2, b2, emb, out, s);
    k_final<<<1, 32>>>(out);
    (void)in_sizes; (void)n_in; (void)out_size;
}

// round 11
// speedup vs baseline: 2.9079x; 1.1702x over previous
#include <cuda_runtime.h>
#include <cuda_bf16.h>
#include <cstdint>
#include <cstddef>

#define NSN  100000
#define NMD  50000
#define EE   600000
#define D    128
#define HOR  8
#define NEG  0.2f
#define GLOG 128   // blocks for k_roll

// ---------------- device scratch ----------------
__device__ float    d_xl[(size_t)NSN * D];
__device__ float    d_xr[(size_t)NMD * D];
__device__ float    d_ew[EE];
__device__ float    d_ssum[NMD];
__device__ float    d_csrc[NSN];
__device__ __align__(16) float d_gacc[D];
__device__ __align__(16) float d_inp[D];
__device__ __align__(16) float d_h[D];
__device__ __align__(16) float d_c[D];
__device__ __align__(16) float d_h2g[D];
__device__ float    d_pm_best[2][GLOG];
__device__ int      d_pm_bi[2][GLOG];
__device__ float    d_pm_bl[2][GLOG];
__device__ float    d_pm_lm[2][GLOG];
__device__ float    d_pm_ls[2][GLOG];
__device__ uint2    d_keys[HOR];
__device__ int      d_is64;
__device__ int      d_flags[HOR];
#define WSTRIDE 136
__device__ __align__(16) uint32_t d_wphl[64 * WSTRIDE];
__device__ __align__(16) uint32_t d_wpll[64 * WSTRIDE];
__device__ __align__(16) uint32_t d_wphr[64 * WSTRIDE];
__device__ __align__(16) uint32_t d_wplr[64 * WSTRIDE];
// transposed LSTM weights: [k][rowpair] float2, rows (2rp, 2rp+1)
__device__ __align__(16) float2 d_wihT[D * 256];
__device__ __align__(16) float2 d_whhT[D * 256];

// ---------------- helpers ----------------
__device__ __forceinline__ int eidx(const void* ei, int is64, long long pos) {
    return is64 ? (int)((const long long*)ei)[pos] : ((const int*)ei)[pos];
}
__device__ __forceinline__ float neginf() { return __int_as_float((int)0xff800000); }

__device__ __forceinline__ uint2 tf2x32(unsigned k0, unsigned k1, unsigned x0, unsigned x1) {
    unsigned k2 = k0 ^ k1 ^ 0x1BD11BDAu;
    x0 += k0; x1 += k1;
#define TFR(r) { x0 += x1; x1 = (x1 << (r)) | (x1 >> (32 - (r))); x1 ^= x0; }
    TFR(13) TFR(15) TFR(26) TFR(6)   x0 += k1; x1 += k2 + 1u;
    TFR(17) TFR(29) TFR(16) TFR(24)  x0 += k2; x1 += k0 + 2u;
    TFR(13) TFR(15) TFR(26) TFR(6)   x0 += k0; x1 += k1 + 3u;
    TFR(17) TFR(29) TFR(16) TFR(24)  x0 += k1; x1 += k2 + 4u;
    TFR(13) TFR(15) TFR(26) TFR(6)   x0 += k2; x1 += k0 + 5u;
#undef TFR
    return make_uint2(x0, x1);
}

__device__ __forceinline__ void lsmerge(float& M, float& S, float m, float s) {
    if (s > 0.f) {
        if (m > M) { S = S * expf(M - m) + s; M = m; }
        else       { S += s * expf(m - M); }
    }
}

__device__ __forceinline__ void mma_bf16(float* c, const uint32_t* a, uint32_t b0, uint32_t b1) {
    asm volatile(
        "mma.sync.aligned.m16n8k16.row.col.f32.bf16.bf16.f32 "
        "{%0,%1,%2,%3}, {%4,%5,%6,%7}, {%8,%9}, {%0,%1,%2,%3};"
        : "+f"(c[0]), "+f"(c[1]), "+f"(c[2]), "+f"(c[3])
        : "r"(a[0]), "r"(a[1]), "r"(a[2]), "r"(a[3]), "r"(b0), "r"(b1));
}

__device__ __forceinline__ uint32_t pack_hi(float e, float o) {
    unsigned a = __bfloat16_as_ushort(__float2bfloat16_rn(e));
    unsigned b = __bfloat16_as_ushort(__float2bfloat16_rn(o));
    return a | (b << 16);
}
__device__ __forceinline__ uint32_t pack_lo(float e, float o) {
    float he = __bfloat162float(__float2bfloat16_rn(e));
    float ho = __bfloat162float(__float2bfloat16_rn(o));
    unsigned a = __bfloat16_as_ushort(__float2bfloat16_rn(e - he));
    unsigned b = __bfloat16_as_ushort(__float2bfloat16_rn(o - ho));
    return a | (b << 16);
}

// ---------------- init ----------------
__global__ void k_init(const void* ei) {
    int i = blockIdx.x * blockDim.x + threadIdx.x;
    if (i < NMD) d_ssum[i] = 0.f;
    if (i < NSN) d_csrc[i] = 0.f;
    if (i < D) { d_gacc[i] = 0.f; d_h[i] = 0.f; d_c[i] = 0.f; }
    if (i < HOR) d_flags[i] = 0;
    if (i == 0) {
        const int* p = (const int*)ei;
        int all0 = 1;
        for (int j = 1; j < 201; j += 2) all0 &= (p[j] == 0);
        d_is64 = all0;
        for (int j = 0; j < HOR; j++) {
            uint2 r = tf2x32(0u, 42u, 0u, (unsigned)j);
            d_keys[j] = make_uint2(r.x, r.y);
        }
    }
}

// ---------------- W [n][k] -> packed bf16 hi/lo [kp][n] (stride 136) ----------------
__global__ void k_wconv(const float* __restrict__ Wl, const float* __restrict__ Wr) {
    int idx = blockIdx.x * blockDim.x + threadIdx.x;
    if (idx >= 64 * 128) return;
    int kp = idx >> 7, n = idx & 127;
    int o = kp * WSTRIDE + n;
    float le = Wl[n * D + 2 * kp], lo = Wl[n * D + 2 * kp + 1];
    d_wphl[o] = pack_hi(le, lo);
    d_wpll[o] = pack_lo(le, lo);
    float re = Wr[n * D + 2 * kp], ro = Wr[n * D + 2 * kp + 1];
    d_wphr[o] = pack_hi(re, ro);
    d_wplr[o] = pack_lo(re, ro);
}

// ---------------- transpose LSTM weights: [row][k] -> [k][rowpair] float2 ----------------
__global__ void k_lstmT(const float* __restrict__ Wih, const float* __restrict__ Whh) {
    int idx = blockIdx.x * blockDim.x + threadIdx.x;   // 32768
    if (idx >= D * 256) return;
    int k = idx >> 8, rp = idx & 255;
    d_wihT[idx] = make_float2(Wih[(2 * rp) * D + k], Wih[(2 * rp + 1) * D + k]);
    d_whhT[idx] = make_float2(Whh[(2 * rp) * D + k], Whh[(2 * rp + 1) * D + k]);
}

// ---------------- HMMA GEMM ----------------
#define SM_GB (64 * WSTRIDE)
__global__ void __launch_bounds__(256, 2) k_gemm_mma(const float* __restrict__ X,
                                                     const uint32_t* __restrict__ gbh,
                                                     const uint32_t* __restrict__ gbl,
                                                     float* __restrict__ Y, int rows) {
    extern __shared__ uint32_t bs[];
    uint32_t* Bh = bs;
    uint32_t* Bl = bs + SM_GB;
    for (int i = threadIdx.x; i < SM_GB / 4; i += 256) {
        ((uint4*)Bh)[i] = ((const uint4*)gbh)[i];
        ((uint4*)Bl)[i] = ((const uint4*)gbl)[i];
    }
    __syncthreads();
    int w = threadIdx.x >> 5, lane = threadIdx.x & 31;
    int q = lane & 3, g = lane >> 2;
    int r0 = blockIdx.x * 128 + w * 16 + g;
    const float* x0 = X + (size_t)(r0 < rows ? r0 : rows - 1) * D;
    const float* x1 = X + (size_t)(r0 + 8 < rows ? r0 + 8 : rows - 1) * D;
    float acc[16][4];
#pragma unroll
    for (int nt = 0; nt < 16; nt++) { acc[nt][0] = acc[nt][1] = acc[nt][2] = acc[nt][3] = 0.f; }
#pragma unroll
    for (int k8 = 0; k8 < 8; k8++) {
        int c0 = k8 * 16 + 2 * q;
        float2 p0 = *(const float2*)(x0 + c0);
        float2 p1 = *(const float2*)(x1 + c0);
        float2 p2 = *(const float2*)(x0 + c0 + 8);
        float2 p3 = *(const float2*)(x1 + c0 + 8);
        uint32_t ah[4], al[4];
        ah[0] = pack_hi(p0.x, p0.y); al[0] = pack_lo(p0.x, p0.y);
        ah[1] = pack_hi(p1.x, p1.y); al[1] = pack_lo(p1.x, p1.y);
        ah[2] = pack_hi(p2.x, p2.y); al[2] = pack_lo(p2.x, p2.y);
        ah[3] = pack_hi(p3.x, p3.y); al[3] = pack_lo(p3.x, p3.y);
        int kb0 = (k8 * 8 + q) * WSTRIDE + g;
        int kb1 = (k8 * 8 + q + 4) * WSTRIDE + g;
#pragma unroll
        for (int nt = 0; nt < 16; nt++) {
            uint32_t bh0 = Bh[kb0 + nt * 8];
            uint32_t bh1 = Bh[kb1 + nt * 8];
            uint32_t bl0 = Bl[kb0 + nt * 8];
            uint32_t bl1 = Bl[kb1 + nt * 8];
            mma_bf16(acc[nt], ah, bh0, bh1);
            mma_bf16(acc[nt], ah, bl0, bl1);
            mma_bf16(acc[nt], al, bh0, bh1);
        }
    }
    bool w0 = r0 < rows, w1 = (r0 + 8) < rows;
#pragma unroll
    for (int nt = 0; nt < 16; nt++) {
        int col = nt * 8 + 2 * q;
        if (w0) *(float2*)(Y + (size_t)r0 * D + col) = make_float2(acc[nt][0], acc[nt][1]);
        if (w1) *(float2*)(Y + (size_t)(r0 + 8) * D + col) = make_float2(acc[nt][2], acc[nt][3]);
    }
}

// ---------------- fused edge pass ----------------
__global__ void __launch_bounds__(256) k_edge12(const void* __restrict__ ei,
                                                const float* __restrict__ att) {
    int lane = threadIdx.x & 31;
    int wid = (blockIdx.x * blockDim.x + threadIdx.x) >> 5;
    int nw = (gridDim.x * blockDim.x) >> 5;
    int is64 = d_is64;
    float4 av = ((const float4*)att)[lane];
    for (int e = wid * 2; e < EE; e += nw * 2) {
        int s1 = eidx(ei, is64, e);
        int dd1 = eidx(ei, is64, (long long)EE + e);
        int s2 = eidx(ei, is64, e + 1);
        int dd2 = eidx(ei, is64, (long long)EE + e + 1);
        float4 l1 = ((const float4*)(d_xl + (size_t)s1 * D))[lane];
        float4 r1 = ((const float4*)(d_xr + (size_t)dd1 * D))[lane];
        float4 l2 = ((const float4*)(d_xl + (size_t)s2 * D))[lane];
        float4 r2 = ((const float4*)(d_xr + (size_t)dd2 * D))[lane];
        float zx, zy, zz, zw, p1, p2;
        zx = l1.x + r1.x; zy = l1.y + r1.y; zz = l1.z + r1.z; zw = l1.w + r1.w;
        zx = zx > 0.f ? zx : NEG * zx; zy = zy > 0.f ? zy : NEG * zy;
        zz = zz > 0.f ? zz : NEG * zz; zw = zw > 0.f ? zw : NEG * zw;
        p1 = av.x * zx + av.y * zy + av.z * zz + av.w * zw;
        zx = l2.x + r2.x; zy = l2.y + r2.y; zz = l2.z + r2.z; zw = l2.w + r2.w;
        zx = zx > 0.f ? zx : NEG * zx; zy = zy > 0.f ? zy : NEG * zy;
        zz = zz > 0.f ? zz : NEG * zz; zw = zw > 0.f ? zw : NEG * zw;
        p2 = av.x * zx + av.y * zy + av.z * zz + av.w * zw;
#pragma unroll
        for (int o = 16; o; o >>= 1) {
            p1 += __shfl_xor_sync(~0u, p1, o);
            p2 += __shfl_xor_sync(~0u, p2, o);
        }
        if (lane == 0) {
            float e1 = expf(p1), e2 = expf(p2);
            d_ew[e] = e1;     atomicAdd(&d_ssum[dd1], e1);
            d_ew[e + 1] = e2; atomicAdd(&d_ssum[dd2], e2);
        }
    }
}

__global__ void k_edge3a(const void* __restrict__ ei) {
    int i = blockIdx.x * blockDim.x + threadIdx.x;
    if (i >= EE) return;
    int is64 = d_is64;
    int src = eidx(ei, is64, i);
    int dst = eidx(ei, is64, (long long)EE + i);
    atomicAdd(&d_csrc[src], d_ew[i] / d_ssum[dst]);
}

__global__ void __launch_bounds__(256) k_dense() {
    __shared__ float sg[D];
    int lane = threadIdx.x & 31, w = threadIdx.x >> 5;
    if (threadIdx.x < D) sg[threadIdx.x] = 0.f;
    __syncthreads();
    int gw = blockIdx.x * 8 + w;
    int nw = gridDim.x * 8;
    float4 acc = make_float4(0.f, 0.f, 0.f, 0.f);
    for (int r = gw; r < NSN; r += nw) {
        float cv = d_csrc[r];
        float4 v = ((const float4*)(d_xl + (size_t)r * D))[lane];
        acc.x += cv * v.x; acc.y += cv * v.y; acc.z += cv * v.z; acc.w += cv * v.w;
    }
    atomicAdd(&sg[lane * 4 + 0], acc.x);
    atomicAdd(&sg[lane * 4 + 1], acc.y);
    atomicAdd(&sg[lane * 4 + 2], acc.z);
    atomicAdd(&sg[lane * 4 + 3], acc.w);
    __syncthreads();
    if (threadIdx.x < D) atomicAdd(&d_gacc[threadIdx.x], sg[threadIdx.x]);
}

__global__ void k_fing(const float* __restrict__ conv_bias) {
    int t = threadIdx.x;
    if (t < D) d_inp[t] = d_gacc[t] * (1.0f / (float)NMD) + conv_bias[t];
}

// ---------------- rollout step: block 0 = producer (sample+LSTM+W1), others wait on flag ----------------
__global__ void __launch_bounds__(256) k_roll(
    const float* __restrict__ bih, const float* __restrict__ bhh,
    const float* __restrict__ W1,  const float* __restrict__ b1,
    const float* __restrict__ W2,  const float* __restrict__ b2,
    const float* __restrict__ emb, float* __restrict__ out, int step) {
    __shared__ float si[D], sh[D], sg[4 * D], snh[D], sh2[D];
    __shared__ float wbest[8], wbl[8], wlm[8], wls[8];
    __shared__ int wbi[8], sAct;
    int t = threadIdx.x, lane = t & 31, w = t >> 5;
    const float NI = neginf();
    int wp = step & 1;
    int pmr = (step - 1) & 1;

    if (blockIdx.x == 0) {
        // ---- phase A: sample prev action ----
        if (step > 0) {
            if (t < 32) {
                float B = NI, BL = 0.f; int BI = 0x7fffffff; float M = NI, S = 0.f;
                for (int i = lane; i < GLOG; i += 32) {
                    float b = d_pm_best[pmr][i]; int bidx = d_pm_bi[pmr][i];
                    if (b > B || (b == B && bidx < BI)) { B = b; BI = bidx; BL = d_pm_bl[pmr][i]; }
                    lsmerge(M, S, d_pm_lm[pmr][i], d_pm_ls[pmr][i]);
                }
#pragma unroll
                for (int o = 16; o; o >>= 1) {
                    float ob = __shfl_xor_sync(~0u, B, o);
                    int oi = __shfl_xor_sync(~0u, BI, o);
                    float ol = __shfl_xor_sync(~0u, BL, o);
                    if (ob > B || (ob == B && oi < BI)) { B = ob; BI = oi; BL = ol; }
                    float om = __shfl_xor_sync(~0u, M, o);
                    float os = __shfl_xor_sync(~0u, S, o);
                    lsmerge(M, S, om, os);
                }
                if (lane == 0) {
                    out[step - 1] = (float)BI;
                    out[HOR + step - 1] = BL - (M + logf(S));
                    sAct = BI;
                }
            }
            __syncthreads();
            if (t < D) si[t] = emb[(size_t)sAct * D + t];
        } else {
            if (t < D) si[t] = d_inp[t];
        }
        if (t < D) sh[t] = d_h[t];
        __syncthreads();

        // ---- LSTM gates via transposed weights (thread t -> rows 2t, 2t+1) ----
        {
            float2 bi_ = ((const float2*)bih)[t];
            float2 bh_ = ((const float2*)bhh)[t];
            float ax = bi_.x + bh_.x, ay = bi_.y + bh_.y;
#pragma unroll 4
            for (int k = 0; k < D; k++) {
                float2 wi = d_wihT[k * 256 + t];
                float2 wh = d_whhT[k * 256 + t];
                float xk = si[k], hk = sh[k];
                ax += wi.x * xk + wh.x * hk;
                ay += wi.y * xk + wh.y * hk;
            }
            sg[2 * t] = ax; sg[2 * t + 1] = ay;
        }
        __syncthreads();
        if (t < D) {
            float ig = 1.f / (1.f + expf(-sg[t]));
            float fg = 1.f / (1.f + expf(-sg[D + t]));
            float gg = tanhf(sg[2 * D + t]);
            float og = 1.f / (1.f + expf(-sg[3 * D + t]));
            float c = fg * d_c[t] + ig * gg;
            float h = og * tanhf(c);
            snh[t] = h;
            d_c[t] = c; d_h[t] = h;
            if (step == HOR - 1) { out[2 * HOR + t] = h; out[2 * HOR + D + t] = c; }
        }
        __syncthreads();
        if (t < D) {
            float a0 = b1[t], a1 = 0.f;
            const float4* w1 = (const float4*)(W1 + (size_t)t * D);
#pragma unroll 8
            for (int k = 0; k < 32; k += 2) {
                float4 a = w1[k];     float4 hv = *(const float4*)(snh + 4 * k);
                float4 b = w1[k + 1]; float4 h2v = *(const float4*)(snh + 4 * k + 4);
                a0 += a.x * hv.x + a.y * hv.y + a.z * hv.z + a.w * hv.w;
                a1 += b.x * h2v.x + b.y * h2v.y + b.z * h2v.z + b.w * h2v.w;
            }
            float a2 = a0 + a1;
            a2 = a2 > 0.f ? a2 : 0.f;
            sh2[t] = a2;
            d_h2g[t] = a2;
        }
        __syncthreads();
        if (t == 0) { __threadfence(); atomicExch(&d_flags[step], 1); }
    } else {
        // consumers: wait for h2
        if (t == 0) { while (atomicAdd(&d_flags[step], 0) == 0) __nanosleep(64); }
        __syncthreads();
        if (t < D) sh2[t] = __ldcg(&d_h2g[t]);
        __syncthreads();
    }

    // ---- phase B: logits + gumbel + online softmax (quad-parallel) ----
    uint2 key = d_keys[step];
    int q = lane & 3, g = lane >> 2;
    float4 hreg[8];
#pragma unroll
    for (int i = 0; i < 8; i++) hreg[i] = ((const float4*)sh2)[i * 4 + q];
    int gw = (blockIdx.x * blockDim.x + t) >> 5;
    int nw = (GLOG * 256) >> 5;
    float best = NI, bl = 0.f; int bi = 0x7fffffff;
    float lm = NI, ls = 0.f;
    for (int base = gw * 32; base < NMD; base += nw * 32) {
        float myl = 0.f;
#pragma unroll
        for (int it = 0; it < 4; it++) {
            int row = base + it * 8 + g;
            float p = 0.f;
            if (row < NMD) {
                const float4* wr = (const float4*)(W2 + (size_t)row * D);
#pragma unroll
                for (int i = 0; i < 8; i++) {
                    float4 wv = wr[i * 4 + q];
                    float4 hv = hreg[i];
                    p += wv.x * hv.x + wv.y * hv.y + wv.z * hv.z + wv.w * hv.w;
                }
            }
            p += __shfl_xor_sync(~0u, p, 1);
            p += __shfl_xor_sync(~0u, p, 2);
            if (q == it) myl = p;
        }
        int myrow = base + q * 8 + g;
        if (myrow < NMD) {
            myl += b2[myrow];
            uint2 tr = tf2x32(key.x, key.y, 0u, (unsigned)myrow);
            unsigned bits = tr.x ^ tr.y;
            float u = __uint_as_float((bits >> 9) | 0x3f800000u) - 1.0f;
            if (u == 0.f) u = 1.17549435e-38f;
            float score = myl - logf(-logf(u));
            if (score > best || (score == best && myrow < bi)) { best = score; bi = myrow; bl = myl; }
            lsmerge(lm, ls, myl, 1.f);
        }
    }
#pragma unroll
    for (int o = 16; o; o >>= 1) {
        float ob = __shfl_xor_sync(~0u, best, o);
        int oi = __shfl_xor_sync(~0u, bi, o);
        float ol = __shfl_xor_sync(~0u, bl, o);
        if (ob > best || (ob == best && oi < bi)) { best = ob; bi = oi; bl = ol; }
        float om = __shfl_xor_sync(~0u, lm, o);
        float os = __shfl_xor_sync(~0u, ls, o);
        lsmerge(lm, ls, om, os);
    }
    if (lane == 0) { wbest[w] = best; wbi[w] = bi; wbl[w] = bl; wlm[w] = lm; wls[w] = ls; }
    __syncthreads();
    if (t == 0) {
        float B = NI, BL = 0.f; int BI = 0x7fffffff; float M = NI, S = 0.f;
        for (int i = 0; i < 8; i++) {
            if (wbest[i] > B || (wbest[i] == B && wbi[i] < BI)) { B = wbest[i]; BI = wbi[i]; BL = wbl[i]; }
            lsmerge(M, S, wlm[i], wls[i]);
        }
        d_pm_best[wp][blockIdx.x] = B; d_pm_bi[wp][blockIdx.x] = BI; d_pm_bl[wp][blockIdx.x] = BL;
        d_pm_lm[wp][blockIdx.x] = M;  d_pm_ls[wp][blockIdx.x] = S;
    }
}

// ---------------- final sample ----------------
__global__ void k_final(float* __restrict__ out) {
    int lane = threadIdx.x;
    const float NI = neginf();
    int pb = (HOR - 1) & 1;
    float B = NI, BL = 0.f; int BI = 0; float M = NI, S = 0.f;
    for (int i = lane; i < GLOG; i += 32) {
        float b = d_pm_best[pb][i]; int bidx = d_pm_bi[pb][i];
        if (b > B || (b == B && bidx < BI)) { B = b; BI = bidx; BL = d_pm_bl[pb][i]; }
        lsmerge(M, S, d_pm_lm[pb][i], d_pm_ls[pb][i]);
    }
#pragma unroll
    for (int o = 16; o; o >>= 1) {
        float ob = __shfl_xor_sync(~0u, B, o);
        int oi = __shfl_xor_sync(~0u, BI, o);
        float ol = __shfl_xor_sync(~0u, BL, o);
        if (ob > B || (ob == B && oi < BI)) { B = ob; BI = oi; BL = ol; }
        float om = __shfl_xor_sync(~0u, M, o);
        float os = __shfl_xor_sync(~0u, S, o);
        lsmerge(M, S, om, os);
    }
    if (lane == 0) {
        out[HOR - 1] = (float)BI;
        out[2 * HOR - 1] = BL - (M + logf(S));
    }
}

// ---------------- launch ----------------
extern "C" void kernel_launch(void* const* d_in, const int* in_sizes, int n_in,
                              void* d_out, int out_size) {
    const float* state_features = (const float*)d_in[0];
    const float* model_features = (const float*)d_in[1];
    const void*  edge_index     = d_in[2];
    const float* W_l   = (const float*)d_in[3];
    const float* W_r   = (const float*)d_in[4];
    const float* att   = (const float*)d_in[5];
    const float* cbias = (const float*)d_in[6];
    const float* Wih   = (const float*)d_in[7];
    const float* Whh   = (const float*)d_in[8];
    const float* bih   = (const float*)d_in[9];
    const float* bhh   = (const float*)d_in[10];
    const float* W1    = (const float*)d_in[11];
    const float* b1    = (const float*)d_in[12];
    const float* W2    = (const float*)d_in[13];
    const float* b2    = (const float*)d_in[14];
    const float* emb   = (const float*)d_in[15];
    float* out = (float*)d_out;

    const int smemB = 2 * SM_GB * (int)sizeof(uint32_t);  // 69632
    cudaFuncSetAttribute(k_gemm_mma, cudaFuncAttributeMaxDynamicSharedMemorySize, smemB);

    float* xl; float* xr;
    cudaGetSymbolAddress((void**)&xl, d_xl);
    cudaGetSymbolAddress((void**)&xr, d_xr);
    uint32_t *whl, *wll, *whr, *wlr;
    cudaGetSymbolAddress((void**)&whl, d_wphl);
    cudaGetSymbolAddress((void**)&wll, d_wpll);
    cudaGetSymbolAddress((void**)&whr, d_wphr);
    cudaGetSymbolAddress((void**)&wlr, d_wplr);

    k_init<<<(NSN + 255) / 256, 256>>>(edge_index);
    k_wconv<<<32, 256>>>(W_l, W_r);
    k_gemm_mma<<<(NMD + 127) / 128, 256, smemB>>>(model_features, whr, wlr, xr, NMD);
    k_gemm_mma<<<(NSN + 127) / 128, 256, smemB>>>(state_features, whl, wll, xl, NSN);  // profiled
    k_lstmT<<<128, 256>>>(Wih, Whh);
    k_edge12<<<1184, 256>>>(edge_index, att);
    k_edge3a<<<(EE + 255) / 256, 256>>>(edge_index);
    k_dense<<<296, 256>>>();
    k_fing<<<1, 128>>>(cbias);
    for (int s = 0; s < HOR; s++)
        k_roll<<<GLOG, 256>>>(bih, bhh, W1, b1, W2, b2, emb, out, s);
    k_final<<<1, 32>>>(out);
    (void)in_sizes; (void)n_in; (void)out_size;
}